// round 1
// baseline (speedup 1.0000x reference)
#include <cuda_runtime.h>
#include <cuda_bf16.h>
#include <math.h>

// Problem constants
#define BATCH 8
#define SEQ   1024
#define CDIM  768
#define HEADS 12
#define HD    64
#define H3    2304
#define HID   3072
#define MROWS (BATCH*SEQ)        // 8192
#define BHEAD (BATCH*HEADS)      // 96
#define LN_EPS 1e-3f

// ---------------- static scratch (no allocations allowed) ----------------
__device__ float g_ln[MROWS * CDIM];        // 25 MB (reused for ln1 and ln2)
__device__ float g_qkv[MROWS * H3];         // 75 MB
__device__ float g_scores[(size_t)BHEAD * SEQ * SEQ]; // 402 MB
__device__ float g_attn[MROWS * CDIM];      // 25 MB
__device__ float g_x1[MROWS * CDIM];        // 25 MB
__device__ float g_h[MROWS * HID];          // 100 MB

// ---------------- reductions ----------------
__device__ __forceinline__ float block_reduce_sum(float v, float* sh) {
    __syncthreads();  // protect sh reuse across calls
    #pragma unroll
    for (int o = 16; o > 0; o >>= 1) v += __shfl_xor_sync(0xffffffffu, v, o);
    int warp = threadIdx.x >> 5, lane = threadIdx.x & 31;
    if (lane == 0) sh[warp] = v;
    __syncthreads();
    if (warp == 0) {
        v = (lane < (blockDim.x >> 5)) ? sh[lane] : 0.0f;
        #pragma unroll
        for (int o = 4; o > 0; o >>= 1) v += __shfl_xor_sync(0xffffffffu, v, o);
        if (lane == 0) sh[0] = v;
    }
    __syncthreads();
    return sh[0];
}

__device__ __forceinline__ float block_reduce_max(float v, float* sh) {
    __syncthreads();
    #pragma unroll
    for (int o = 16; o > 0; o >>= 1) v = fmaxf(v, __shfl_xor_sync(0xffffffffu, v, o));
    int warp = threadIdx.x >> 5, lane = threadIdx.x & 31;
    if (lane == 0) sh[warp] = v;
    __syncthreads();
    if (warp == 0) {
        v = (lane < (blockDim.x >> 5)) ? sh[lane] : -INFINITY;
        #pragma unroll
        for (int o = 4; o > 0; o >>= 1) v = fmaxf(v, __shfl_xor_sync(0xffffffffu, v, o));
        if (lane == 0) sh[0] = v;
    }
    __syncthreads();
    return sh[0];
}

// ---------------- LayerNorm: one block per row (768 = 256*3) ----------------
__global__ void ln_kernel(const float* __restrict__ x, const float* __restrict__ g,
                          const float* __restrict__ b, float* __restrict__ out) {
    __shared__ float sh[32];
    int row = blockIdx.x;
    int t = threadIdx.x;
    const float* xr = x + (size_t)row * CDIM;
    float v0 = xr[t], v1 = xr[t + 256], v2 = xr[t + 512];
    float s = block_reduce_sum(v0 + v1 + v2, sh);
    float mu = s * (1.0f / CDIM);
    float d0 = v0 - mu, d1 = v1 - mu, d2 = v2 - mu;
    float s2 = block_reduce_sum(d0 * d0 + d1 * d1 + d2 * d2, sh);
    float rstd = rsqrtf(s2 * (1.0f / CDIM) + LN_EPS);
    float* outr = out + (size_t)row * CDIM;
    outr[t]       = d0 * rstd * g[t]       + b[t];
    outr[t + 256] = d1 * rstd * g[t + 256] + b[t + 256];
    outr[t + 512] = d2 * rstd * g[t + 512] + b[t + 512];
}

// ---------------- SGEMM 128x128x8, 256 threads, 8x8 microtile ----------------
// C[M,N] = A[M,K] @ B[K,N] + bias, with epilogue modes:
//   MODE 0: plain
//   MODE 1: res + gamma * (AB + bias)  (residual layerscale)
//   MODE 2: gelu(AB + bias) exact (erf)
template<int MODE>
__global__ __launch_bounds__(256) void sgemm_kernel(
    const float* __restrict__ A, const float* __restrict__ B,
    const float* __restrict__ bias, const float* __restrict__ res,
    const float* __restrict__ gamma, float* __restrict__ C,
    int M, int N, int K)
{
    __shared__ __align__(16) float As[8][128]; // [k][m] transposed
    __shared__ __align__(16) float Bs[8][128]; // [k][n]

    int tid = threadIdx.x;
    int bx = blockIdx.x, by = blockIdx.y;
    int tx = tid & 15, ty = tid >> 4;

    // A load mapping: 128 rows x 8 cols -> 256 float4 (2 per row)
    int arow = tid >> 1;
    int acol = (tid & 1) * 4;
    // B load mapping: 8 rows x 128 cols -> 256 float4 (32 per row)
    int brow = tid >> 5;
    int bcol = (tid & 31) * 4;

    const float* Aptr = A + (size_t)(by * 128 + arow) * K + acol;
    const float* Bptr = B + (size_t)brow * N + bx * 128 + bcol;

    float acc[8][8];
    #pragma unroll
    for (int i = 0; i < 8; i++)
        #pragma unroll
        for (int j = 0; j < 8; j++) acc[i][j] = 0.0f;

    for (int k0 = 0; k0 < K; k0 += 8) {
        float4 a4 = *(const float4*)(Aptr + k0);
        float4 b4 = *(const float4*)(Bptr + (size_t)k0 * N);
        As[acol + 0][arow] = a4.x;
        As[acol + 1][arow] = a4.y;
        As[acol + 2][arow] = a4.z;
        As[acol + 3][arow] = a4.w;
        *(float4*)&Bs[brow][bcol] = b4;
        __syncthreads();

        #pragma unroll
        for (int k = 0; k < 8; k++) {
            float4 a0 = *(const float4*)&As[k][ty * 8];
            float4 a1 = *(const float4*)&As[k][ty * 8 + 4];
            float4 b0 = *(const float4*)&Bs[k][tx * 8];
            float4 b1 = *(const float4*)&Bs[k][tx * 8 + 4];
            float av[8] = {a0.x, a0.y, a0.z, a0.w, a1.x, a1.y, a1.z, a1.w};
            float bv[8] = {b0.x, b0.y, b0.z, b0.w, b1.x, b1.y, b1.z, b1.w};
            #pragma unroll
            for (int i = 0; i < 8; i++)
                #pragma unroll
                for (int j = 0; j < 8; j++)
                    acc[i][j] = fmaf(av[i], bv[j], acc[i][j]);
        }
        __syncthreads();
    }

    // epilogue
    #pragma unroll
    for (int i = 0; i < 8; i++) {
        int gm = by * 128 + ty * 8 + i;
        size_t rowoff = (size_t)gm * N + bx * 128 + tx * 8;
        #pragma unroll
        for (int jv = 0; jv < 2; jv++) {
            int gn = bx * 128 + tx * 8 + jv * 4;
            float4 v;
            v.x = acc[i][jv * 4 + 0] + bias[gn + 0];
            v.y = acc[i][jv * 4 + 1] + bias[gn + 1];
            v.z = acc[i][jv * 4 + 2] + bias[gn + 2];
            v.w = acc[i][jv * 4 + 3] + bias[gn + 3];
            if (MODE == 1) {
                float4 r = *(const float4*)(res + rowoff + jv * 4);
                v.x = r.x + gamma[gn + 0] * v.x;
                v.y = r.y + gamma[gn + 1] * v.y;
                v.z = r.z + gamma[gn + 2] * v.z;
                v.w = r.w + gamma[gn + 3] * v.w;
            } else if (MODE == 2) {
                v.x = 0.5f * v.x * (1.0f + erff(v.x * 0.70710678118654752f));
                v.y = 0.5f * v.y * (1.0f + erff(v.y * 0.70710678118654752f));
                v.z = 0.5f * v.z * (1.0f + erff(v.z * 0.70710678118654752f));
                v.w = 0.5f * v.w * (1.0f + erff(v.w * 0.70710678118654752f));
            }
            *(float4*)(C + rowoff + jv * 4) = v;
        }
    }
}

// ---------------- attention scores: S[bh,i,j] = 0.125 * Q[i,:]·K[j,:] ----------------
// grid (16 jtiles, 16 itiles, 96 bh), 256 threads, 64x64 tile, K=64 (full)
__global__ __launch_bounds__(256) void attn_scores_kernel(const float* __restrict__ qkv,
                                                          float* __restrict__ scores) {
    __shared__ __align__(16) float Qt[64][64]; // [d][i]
    __shared__ __align__(16) float Kt[64][64]; // [d][j]
    int bh = blockIdx.z;
    int b = bh / HEADS, h = bh % HEADS;
    int i0 = blockIdx.y * 64, j0 = blockIdx.x * 64;
    int tid = threadIdx.x;

    const float* Qb = qkv + (size_t)b * SEQ * H3 + h * HD;
    const float* Kb = Qb + CDIM;

    #pragma unroll
    for (int t = 0; t < 4; t++) {
        int idx = tid + t * 256;
        int row = idx >> 4;           // 0..63
        int c4 = (idx & 15) * 4;      // 0..60
        float4 q = *(const float4*)(Qb + (size_t)(i0 + row) * H3 + c4);
        float4 k = *(const float4*)(Kb + (size_t)(j0 + row) * H3 + c4);
        Qt[c4 + 0][row] = q.x; Qt[c4 + 1][row] = q.y;
        Qt[c4 + 2][row] = q.z; Qt[c4 + 3][row] = q.w;
        Kt[c4 + 0][row] = k.x; Kt[c4 + 1][row] = k.y;
        Kt[c4 + 2][row] = k.z; Kt[c4 + 3][row] = k.w;
    }
    __syncthreads();

    int tx = tid & 15, ty = tid >> 4;
    int li = ty * 4, lj = tx * 4;
    float acc[4][4];
    #pragma unroll
    for (int i = 0; i < 4; i++)
        #pragma unroll
        for (int j = 0; j < 4; j++) acc[i][j] = 0.0f;

    #pragma unroll 8
    for (int d = 0; d < 64; d++) {
        float4 q = *(const float4*)&Qt[d][li];
        float4 k = *(const float4*)&Kt[d][lj];
        float qv[4] = {q.x, q.y, q.z, q.w};
        float kv[4] = {k.x, k.y, k.z, k.w};
        #pragma unroll
        for (int i = 0; i < 4; i++)
            #pragma unroll
            for (int j = 0; j < 4; j++)
                acc[i][j] = fmaf(qv[i], kv[j], acc[i][j]);
    }

    const float scale = 0.125f; // 64^-0.5
    float* Sb = scores + ((size_t)bh << 20);
    #pragma unroll
    for (int i = 0; i < 4; i++) {
        float4 v;
        v.x = acc[i][0] * scale; v.y = acc[i][1] * scale;
        v.z = acc[i][2] * scale; v.w = acc[i][3] * scale;
        *(float4*)(Sb + (size_t)(i0 + li + i) * SEQ + j0 + lj) = v;
    }
}

// ---------------- softmax over rows of 1024 (in place) ----------------
__global__ __launch_bounds__(256) void softmax_kernel(float* __restrict__ scores) {
    __shared__ float sh[32];
    size_t row = blockIdx.x;
    float* p = scores + row * SEQ;
    float4 v = ((float4*)p)[threadIdx.x];
    float mx = fmaxf(fmaxf(v.x, v.y), fmaxf(v.z, v.w));
    mx = block_reduce_max(mx, sh);
    v.x = expf(v.x - mx); v.y = expf(v.y - mx);
    v.z = expf(v.z - mx); v.w = expf(v.w - mx);
    float s = block_reduce_sum(v.x + v.y + v.z + v.w, sh);
    float inv = 1.0f / s;
    v.x *= inv; v.y *= inv; v.z *= inv; v.w *= inv;
    ((float4*)p)[threadIdx.x] = v;
}

// ---------------- O = P @ V : grid (16 itiles, 96 bh), 64 rows x 64 d ----------------
__global__ __launch_bounds__(256) void attn_av_kernel(const float* __restrict__ scores,
                                                      const float* __restrict__ qkv,
                                                      float* __restrict__ attn_out) {
    __shared__ __align__(16) float Pt[64][64]; // [j][i]
    __shared__ __align__(16) float Vs[64][64]; // [j][d]
    int bh = blockIdx.y;
    int b = bh / HEADS, h = bh % HEADS;
    int i0 = blockIdx.x * 64;
    int tid = threadIdx.x;
    int tx = tid & 15, ty = tid >> 4;
    int li = ty * 4, ld = tx * 4;

    const float* Sb = scores + ((size_t)bh << 20);
    const float* Vb = qkv + (size_t)b * SEQ * H3 + 2 * CDIM + h * HD;

    float acc[4][4];
    #pragma unroll
    for (int i = 0; i < 4; i++)
        #pragma unroll
        for (int j = 0; j < 4; j++) acc[i][j] = 0.0f;

    for (int jt = 0; jt < 16; jt++) {
        int j0 = jt * 64;
        #pragma unroll
        for (int t = 0; t < 4; t++) {
            int idx = tid + t * 256;
            int row = idx >> 4;
            int c4 = (idx & 15) * 4;
            float4 pv = *(const float4*)(Sb + (size_t)(i0 + row) * SEQ + j0 + c4);
            Pt[c4 + 0][row] = pv.x; Pt[c4 + 1][row] = pv.y;
            Pt[c4 + 2][row] = pv.z; Pt[c4 + 3][row] = pv.w;
            float4 vv = *(const float4*)(Vb + (size_t)(j0 + row) * H3 + c4);
            *(float4*)&Vs[row][c4] = vv;
        }
        __syncthreads();

        #pragma unroll 8
        for (int j = 0; j < 64; j++) {
            float4 p4 = *(const float4*)&Pt[j][li];
            float4 v4 = *(const float4*)&Vs[j][ld];
            float pv[4] = {p4.x, p4.y, p4.z, p4.w};
            float vv[4] = {v4.x, v4.y, v4.z, v4.w};
            #pragma unroll
            for (int i = 0; i < 4; i++)
                #pragma unroll
                for (int d = 0; d < 4; d++)
                    acc[i][d] = fmaf(pv[i], vv[d], acc[i][d]);
        }
        __syncthreads();
    }

    #pragma unroll
    for (int i = 0; i < 4; i++) {
        size_t m = (size_t)b * SEQ + i0 + li + i;
        float4 v = {acc[i][0], acc[i][1], acc[i][2], acc[i][3]};
        *(float4*)(attn_out + m * CDIM + h * HD + ld) = v;
    }
}

// ---------------- launch ----------------
extern "C" void kernel_launch(void* const* d_in, const int* in_sizes, int n_in,
                              void* d_out, int out_size) {
    const float* x      = (const float*)d_in[0];
    const float* ln1_g  = (const float*)d_in[1];
    const float* ln1_b  = (const float*)d_in[2];
    const float* w_qkv  = (const float*)d_in[3];
    const float* b_qkv  = (const float*)d_in[4];
    const float* w_proj = (const float*)d_in[5];
    const float* b_proj = (const float*)d_in[6];
    const float* gamma1 = (const float*)d_in[7];
    const float* ln2_g  = (const float*)d_in[8];
    const float* ln2_b  = (const float*)d_in[9];
    const float* w_fc1  = (const float*)d_in[10];
    const float* b_fc1  = (const float*)d_in[11];
    const float* w_fc2  = (const float*)d_in[12];
    const float* b_fc2  = (const float*)d_in[13];
    const float* gamma2 = (const float*)d_in[14];
    float* out = (float*)d_out;

    float *ln, *qkv, *sc, *attn, *x1, *h;
    cudaGetSymbolAddress((void**)&ln,   g_ln);
    cudaGetSymbolAddress((void**)&qkv,  g_qkv);
    cudaGetSymbolAddress((void**)&sc,   g_scores);
    cudaGetSymbolAddress((void**)&attn, g_attn);
    cudaGetSymbolAddress((void**)&x1,   g_x1);
    cudaGetSymbolAddress((void**)&h,    g_h);

    // 1) ln1
    ln_kernel<<<MROWS, 256>>>(x, ln1_g, ln1_b, ln);
    // 2) qkv = ln @ w_qkv + b_qkv
    sgemm_kernel<0><<<dim3(H3 / 128, MROWS / 128), 256>>>(ln, w_qkv, b_qkv, nullptr, nullptr, qkv, MROWS, H3, CDIM);
    // 3) scores
    attn_scores_kernel<<<dim3(16, 16, BHEAD), 256>>>(qkv, sc);
    // 4) softmax
    softmax_kernel<<<BHEAD * SEQ, 256>>>(sc);
    // 5) O = P @ V
    attn_av_kernel<<<dim3(16, BHEAD), 256>>>(sc, qkv, attn);
    // 6) x1 = x + gamma1 * (attn @ w_proj + b_proj)
    sgemm_kernel<1><<<dim3(CDIM / 128, MROWS / 128), 256>>>(attn, w_proj, b_proj, x, gamma1, x1, MROWS, CDIM, CDIM);
    // 7) ln2
    ln_kernel<<<MROWS, 256>>>(x1, ln2_g, ln2_b, ln);
    // 8) h = gelu(ln2 @ w_fc1 + b_fc1)
    sgemm_kernel<2><<<dim3(HID / 128, MROWS / 128), 256>>>(ln, w_fc1, b_fc1, nullptr, nullptr, h, MROWS, HID, CDIM);
    // 9) out = x1 + gamma2 * (h @ w_fc2 + b_fc2)
    sgemm_kernel<1><<<dim3(CDIM / 128, MROWS / 128), 256>>>(h, w_fc2, b_fc2, x1, gamma2, out, MROWS, CDIM, HID);
}

// round 2
// speedup vs baseline: 5.8976x; 5.8976x over previous
#include <cuda_runtime.h>
#include <cuda_bf16.h>
#include <math.h>
#include <stdint.h>

// Problem constants
#define BATCH 8
#define SEQ   1024
#define CDIM  768
#define HEADS 12
#define HD    64
#define H3    2304
#define HID   3072
#define MROWS (BATCH*SEQ)        // 8192
#define BHEAD (BATCH*HEADS)      // 96
#define LN_EPS 1e-3f

// ---------------- static scratch ----------------
__device__ __nv_bfloat16 g_ln_bf[MROWS * CDIM];
__device__ __nv_bfloat16 g_qkv_bf[MROWS * H3];
__device__ float         g_scores[(size_t)BHEAD * SEQ * SEQ];   // 402 MB
__device__ __nv_bfloat16 g_p[(size_t)BHEAD * SEQ * SEQ];        // 201 MB
__device__ __nv_bfloat16 g_attn_bf[MROWS * CDIM];
__device__ float         g_x1[MROWS * CDIM];
__device__ __nv_bfloat16 g_h_bf[MROWS * HID];
__device__ __nv_bfloat16 g_wqkv_bf[CDIM * H3];
__device__ __nv_bfloat16 g_wproj_bf[CDIM * CDIM];
__device__ __nv_bfloat16 g_wfc1_bf[CDIM * HID];
__device__ __nv_bfloat16 g_wfc2_bf[HID * CDIM];

// ---------------- PTX helpers ----------------
__device__ __forceinline__ uint32_t cvta_smem(const void* p) {
    return (uint32_t)__cvta_generic_to_shared(p);
}
__device__ __forceinline__ void ldsm_x4(uint32_t& r0, uint32_t& r1, uint32_t& r2, uint32_t& r3, uint32_t a) {
    asm volatile("ldmatrix.sync.aligned.m8n8.x4.shared.b16 {%0,%1,%2,%3},[%4];"
                 : "=r"(r0), "=r"(r1), "=r"(r2), "=r"(r3) : "r"(a));
}
__device__ __forceinline__ void ldsm_x4_t(uint32_t& r0, uint32_t& r1, uint32_t& r2, uint32_t& r3, uint32_t a) {
    asm volatile("ldmatrix.sync.aligned.m8n8.x4.trans.shared.b16 {%0,%1,%2,%3},[%4];"
                 : "=r"(r0), "=r"(r1), "=r"(r2), "=r"(r3) : "r"(a));
}
__device__ __forceinline__ void mma_bf16(float* c, const uint32_t* a, const uint32_t* b) {
    asm volatile("mma.sync.aligned.m16n8k16.row.col.f32.bf16.bf16.f32 "
                 "{%0,%1,%2,%3},{%4,%5,%6,%7},{%8,%9},{%0,%1,%2,%3};"
                 : "+f"(c[0]), "+f"(c[1]), "+f"(c[2]), "+f"(c[3])
                 : "r"(a[0]), "r"(a[1]), "r"(a[2]), "r"(a[3]), "r"(b[0]), "r"(b[1]));
}
__device__ __forceinline__ void cp16(uint32_t saddr, const void* g) {
    asm volatile("cp.async.cg.shared.global [%0],[%1],16;" :: "r"(saddr), "l"(g));
}
__device__ __forceinline__ void cp_commit() { asm volatile("cp.async.commit_group;"); }
__device__ __forceinline__ void cp_wait0()  { asm volatile("cp.async.wait_group 0;"); }
__device__ __forceinline__ void cp_wait1()  { asm volatile("cp.async.wait_group 1;"); }

// ---------------- fp32 -> bf16 convert ----------------
__global__ void f2bf_kernel(const float* __restrict__ in, __nv_bfloat16* __restrict__ out, int n) {
    int i = (blockIdx.x * blockDim.x + threadIdx.x) * 4;
    if (i < n) {
        float4 v = *(const float4*)(in + i);
        __nv_bfloat162* o = (__nv_bfloat162*)(out + i);
        o[0] = __float22bfloat162_rn(make_float2(v.x, v.y));
        o[1] = __float22bfloat162_rn(make_float2(v.z, v.w));
    }
}

// ---------------- reductions ----------------
__device__ __forceinline__ float block_reduce_sum(float v, float* sh) {
    __syncthreads();
    #pragma unroll
    for (int o = 16; o > 0; o >>= 1) v += __shfl_xor_sync(0xffffffffu, v, o);
    int warp = threadIdx.x >> 5, lane = threadIdx.x & 31;
    if (lane == 0) sh[warp] = v;
    __syncthreads();
    if (warp == 0) {
        v = (lane < (blockDim.x >> 5)) ? sh[lane] : 0.0f;
        #pragma unroll
        for (int o = 4; o > 0; o >>= 1) v += __shfl_xor_sync(0xffffffffu, v, o);
        if (lane == 0) sh[0] = v;
    }
    __syncthreads();
    return sh[0];
}
__device__ __forceinline__ float block_reduce_max(float v, float* sh) {
    __syncthreads();
    #pragma unroll
    for (int o = 16; o > 0; o >>= 1) v = fmaxf(v, __shfl_xor_sync(0xffffffffu, v, o));
    int warp = threadIdx.x >> 5, lane = threadIdx.x & 31;
    if (lane == 0) sh[warp] = v;
    __syncthreads();
    if (warp == 0) {
        v = (lane < (blockDim.x >> 5)) ? sh[lane] : -INFINITY;
        #pragma unroll
        for (int o = 4; o > 0; o >>= 1) v = fmaxf(v, __shfl_xor_sync(0xffffffffu, v, o));
        if (lane == 0) sh[0] = v;
    }
    __syncthreads();
    return sh[0];
}

// ---------------- LayerNorm (fp32 in -> bf16 out), one block/row ----------------
__global__ void ln_kernel(const float* __restrict__ x, const float* __restrict__ g,
                          const float* __restrict__ b, __nv_bfloat16* __restrict__ out) {
    __shared__ float sh[32];
    int row = blockIdx.x;
    int t = threadIdx.x;
    const float* xr = x + (size_t)row * CDIM;
    float v0 = xr[t], v1 = xr[t + 256], v2 = xr[t + 512];
    float s = block_reduce_sum(v0 + v1 + v2, sh);
    float mu = s * (1.0f / CDIM);
    float d0 = v0 - mu, d1 = v1 - mu, d2 = v2 - mu;
    float s2 = block_reduce_sum(d0 * d0 + d1 * d1 + d2 * d2, sh);
    float rstd = rsqrtf(s2 * (1.0f / CDIM) + LN_EPS);
    __nv_bfloat16* outr = out + (size_t)row * CDIM;
    outr[t]       = __float2bfloat16(d0 * rstd * g[t]       + b[t]);
    outr[t + 256] = __float2bfloat16(d1 * rstd * g[t + 256] + b[t + 256]);
    outr[t + 512] = __float2bfloat16(d2 * rstd * g[t + 512] + b[t + 512]);
}

// ---------------- bf16 GEMM 128x128x32, 256 threads, 8 warps (2x4) ----------------
// C[M,N] = A[M,K] @ B[K,N] + bias; MODE 0: bias->bf16; MODE 1: res+gamma*(.)->fp32;
// MODE 2: gelu(.)->bf16
template<int MODE>
__global__ __launch_bounds__(256) void gemm_bf16(
    const __nv_bfloat16* __restrict__ A, const __nv_bfloat16* __restrict__ B,
    const float* __restrict__ bias, const float* __restrict__ res,
    const float* __restrict__ gamma, void* __restrict__ Cout,
    int M, int N, int K)
{
    __shared__ __align__(16) __nv_bfloat16 As[2][128 * 32];
    __shared__ __align__(16) __nv_bfloat16 Bs[2][32 * 128];

    int tid = threadIdx.x, lane = tid & 31, warp = tid >> 5;
    int wm = (warp >> 2) * 64, wn = (warp & 3) * 32;
    int bx = blockIdx.x, by = blockIdx.y;

    // global load mapping
    int a_row = tid >> 2, a_c = tid & 3;          // +256 -> rows 64..127
    int b_row = tid >> 4, b_c = tid & 15;         // +256 -> rows 16..31
    const __nv_bfloat16* Ag = A + (size_t)(by * 128 + a_row) * K + a_c * 8;
    const __nv_bfloat16* Ag2 = Ag + (size_t)64 * K;
    const __nv_bfloat16* Bg = B + (size_t)b_row * N + bx * 128 + b_c * 8;
    const __nv_bfloat16* Bg2 = Bg + (size_t)16 * N;

    uint32_t asb[2], bsb[2];
    asb[0] = cvta_smem(As[0]); asb[1] = cvta_smem(As[1]);
    bsb[0] = cvta_smem(Bs[0]); bsb[1] = cvta_smem(Bs[1]);
    // smem store offsets (bytes), swizzled
    uint32_t a_off  = a_row * 64 + ((a_c ^ ((a_row >> 1) & 3)) * 16);
    uint32_t a_off2 = (a_row + 64) * 64 + ((a_c ^ (((a_row + 64) >> 1) & 3)) * 16);
    uint32_t b_off  = b_row * 256 + ((b_c ^ (b_row & 7)) * 16);
    uint32_t b_off2 = (b_row + 16) * 256 + ((b_c ^ ((b_row + 16) & 7)) * 16);

    float acc[4][4][4];
    #pragma unroll
    for (int i = 0; i < 4; i++)
        #pragma unroll
        for (int j = 0; j < 4; j++)
            #pragma unroll
            for (int k = 0; k < 4; k++) acc[i][j][k] = 0.0f;

    int KB = K >> 5;
    // prologue: stage 0
    cp16(asb[0] + a_off,  Ag);
    cp16(asb[0] + a_off2, Ag2);
    cp16(bsb[0] + b_off,  Bg);
    cp16(bsb[0] + b_off2, Bg2);
    cp_commit();

    // precompute fragment smem addresses (stage-relative byte offsets)
    uint32_t a_frag_off[4][2], b_frag_off[2][2];
    #pragma unroll
    for (int mi = 0; mi < 4; mi++) {
        int r = wm + mi * 16 + (lane & 15);
        #pragma unroll
        for (int k16 = 0; k16 < 2; k16++) {
            int ch = k16 * 2 + (lane >> 4);
            a_frag_off[mi][k16] = r * 64 + ((ch ^ ((r >> 1) & 3)) * 16);
        }
    }
    #pragma unroll
    for (int nh = 0; nh < 2; nh++) {
        #pragma unroll
        for (int k16 = 0; k16 < 2; k16++) {
            int r = k16 * 16 + (lane & 15);
            int ch = (wn >> 3) + nh * 2 + (lane >> 4);
            b_frag_off[nh][k16] = r * 256 + ((ch ^ (r & 7)) * 16);
        }
    }

    for (int kb = 0; kb < KB; kb++) {
        if (kb + 1 < KB) {
            int st = (kb + 1) & 1;
            size_t ka = (size_t)(kb + 1) * 32;
            cp16(asb[st] + a_off,  Ag + ka);
            cp16(asb[st] + a_off2, Ag2 + ka);
            cp16(bsb[st] + b_off,  Bg + ka * N);
            cp16(bsb[st] + b_off2, Bg2 + ka * N);
            cp_commit();
            cp_wait1();
        } else {
            cp_wait0();
        }
        __syncthreads();
        int st = kb & 1;
        #pragma unroll
        for (int k16 = 0; k16 < 2; k16++) {
            uint32_t af[4][4];
            #pragma unroll
            for (int mi = 0; mi < 4; mi++)
                ldsm_x4(af[mi][0], af[mi][1], af[mi][2], af[mi][3], asb[st] + a_frag_off[mi][k16]);
            uint32_t bf[4][2];
            #pragma unroll
            for (int nh = 0; nh < 2; nh++) {
                uint32_t t0, t1, t2, t3;
                ldsm_x4_t(t0, t1, t2, t3, bsb[st] + b_frag_off[nh][k16]);
                bf[nh * 2][0] = t0; bf[nh * 2][1] = t1;
                bf[nh * 2 + 1][0] = t2; bf[nh * 2 + 1][1] = t3;
            }
            #pragma unroll
            for (int mi = 0; mi < 4; mi++)
                #pragma unroll
                for (int ni = 0; ni < 4; ni++)
                    mma_bf16(acc[mi][ni], af[mi], bf[ni]);
        }
        __syncthreads();
    }

    // epilogue
    #pragma unroll
    for (int mi = 0; mi < 4; mi++) {
        #pragma unroll
        for (int ni = 0; ni < 4; ni++) {
            #pragma unroll
            for (int hh = 0; hh < 2; hh++) {
                int row = by * 128 + wm + mi * 16 + (lane >> 2) + hh * 8;
                int col = bx * 128 + wn + ni * 8 + (lane & 3) * 2;
                float vx = acc[mi][ni][hh * 2]     + bias[col];
                float vy = acc[mi][ni][hh * 2 + 1] + bias[col + 1];
                size_t off = (size_t)row * N + col;
                if (MODE == 1) {
                    float* C = (float*)Cout;
                    float2 r = *(const float2*)(res + off);
                    float2 o;
                    o.x = r.x + gamma[col]     * vx;
                    o.y = r.y + gamma[col + 1] * vy;
                    *(float2*)(C + off) = o;
                } else {
                    if (MODE == 2) {
                        vx = 0.5f * vx * (1.0f + erff(vx * 0.70710678118654752f));
                        vy = 0.5f * vy * (1.0f + erff(vy * 0.70710678118654752f));
                    }
                    __nv_bfloat16* C = (__nv_bfloat16*)Cout;
                    *(__nv_bfloat162*)(C + off) = __float22bfloat162_rn(make_float2(vx, vy));
                }
            }
        }
    }
}

// ---------------- attention scores: S = 0.125 * Q@K^T, 128x128 tile, k=64 ----------------
__global__ __launch_bounds__(256) void attn_scores_kernel(const __nv_bfloat16* __restrict__ qkv,
                                                          float* __restrict__ scores) {
    __shared__ __align__(16) __nv_bfloat16 Qs[128 * 64];
    __shared__ __align__(16) __nv_bfloat16 Ks[128 * 64];
    int bh = blockIdx.z;
    int b = bh / HEADS, h = bh % HEADS;
    int i0 = blockIdx.y * 128, j0 = blockIdx.x * 128;
    int tid = threadIdx.x, lane = tid & 31, warp = tid >> 5;
    int wm = (warp >> 2) * 64, wn = (warp & 3) * 32;

    const __nv_bfloat16* Qb = qkv + (size_t)b * SEQ * H3 + h * HD;
    const __nv_bfloat16* Kb = Qb + CDIM;

    // load 128x64 tiles (1024 chunks each -> 4 per thread)
    #pragma unroll
    for (int t = 0; t < 4; t++) {
        int idx = tid + t * 256;
        int r = idx >> 3, c = idx & 7;
        uint32_t off = r * 128 + ((c ^ (r & 7)) * 16);
        uint4 q = *(const uint4*)(Qb + (size_t)(i0 + r) * H3 + c * 8);
        uint4 k = *(const uint4*)(Kb + (size_t)(j0 + r) * H3 + c * 8);
        *(uint4*)((char*)Qs + off) = q;
        *(uint4*)((char*)Ks + off) = k;
    }
    __syncthreads();
    uint32_t qsb = cvta_smem(Qs), ksb = cvta_smem(Ks);

    float acc[4][4][4];
    #pragma unroll
    for (int i = 0; i < 4; i++)
        #pragma unroll
        for (int j = 0; j < 4; j++)
            #pragma unroll
            for (int k = 0; k < 4; k++) acc[i][j][k] = 0.0f;

    #pragma unroll
    for (int k16 = 0; k16 < 4; k16++) {
        uint32_t af[4][4];
        #pragma unroll
        for (int mi = 0; mi < 4; mi++) {
            int r = wm + mi * 16 + (lane & 15);
            int ch = k16 * 2 + (lane >> 4);
            ldsm_x4(af[mi][0], af[mi][1], af[mi][2], af[mi][3],
                    qsb + r * 128 + ((ch ^ (r & 7)) * 16));
        }
        uint32_t bf[4][2];
        #pragma unroll
        for (int nh = 0; nh < 2; nh++) {
            int r = wn + nh * 16 + (lane & 15);
            int ch = k16 * 2 + (lane >> 4);
            uint32_t t0, t1, t2, t3;
            ldsm_x4(t0, t1, t2, t3, ksb + r * 128 + ((ch ^ (r & 7)) * 16));
            bf[nh * 2][0] = t0; bf[nh * 2][1] = t2;       // n0-7 : {k0-7, k8-15}
            bf[nh * 2 + 1][0] = t1; bf[nh * 2 + 1][1] = t3; // n8-15
        }
        #pragma unroll
        for (int mi = 0; mi < 4; mi++)
            #pragma unroll
            for (int ni = 0; ni < 4; ni++)
                mma_bf16(acc[mi][ni], af[mi], bf[ni]);
    }

    float* Sb = scores + ((size_t)bh << 20);
    #pragma unroll
    for (int mi = 0; mi < 4; mi++)
        #pragma unroll
        for (int ni = 0; ni < 4; ni++)
            #pragma unroll
            for (int hh = 0; hh < 2; hh++) {
                int row = i0 + wm + mi * 16 + (lane >> 2) + hh * 8;
                int col = j0 + wn + ni * 8 + (lane & 3) * 2;
                float2 v;
                v.x = acc[mi][ni][hh * 2] * 0.125f;
                v.y = acc[mi][ni][hh * 2 + 1] * 0.125f;
                *(float2*)(Sb + (size_t)row * SEQ + col) = v;
            }
}

// ---------------- softmax row of 1024: fp32 in -> bf16 out ----------------
__global__ __launch_bounds__(256) void softmax_kernel(const float* __restrict__ scores,
                                                      __nv_bfloat16* __restrict__ P) {
    __shared__ float sh[32];
    size_t row = blockIdx.x;
    const float* p = scores + row * SEQ;
    int t = threadIdx.x;
    float4 v = ((const float4*)p)[t];
    float mx = fmaxf(fmaxf(v.x, v.y), fmaxf(v.z, v.w));
    mx = block_reduce_max(mx, sh);
    v.x = expf(v.x - mx); v.y = expf(v.y - mx);
    v.z = expf(v.z - mx); v.w = expf(v.w - mx);
    float s = block_reduce_sum(v.x + v.y + v.z + v.w, sh);
    float inv = 1.0f / s;
    __nv_bfloat162* o = (__nv_bfloat162*)(P + row * SEQ);
    o[t * 2]     = __float22bfloat162_rn(make_float2(v.x * inv, v.y * inv));
    o[t * 2 + 1] = __float22bfloat162_rn(make_float2(v.z * inv, v.w * inv));
}

// ---------------- O = P @ V : 128(i) x 64(d) tile, loop j by 128 ----------------
__global__ __launch_bounds__(256) void attn_av_kernel(const __nv_bfloat16* __restrict__ P,
                                                      const __nv_bfloat16* __restrict__ qkv,
                                                      __nv_bfloat16* __restrict__ attn_out) {
    __shared__ __align__(16) __nv_bfloat16 Ps[128 * 128];
    __shared__ __align__(16) __nv_bfloat16 Vs[128 * 64];
    int bh = blockIdx.y;
    int b = bh / HEADS, h = bh % HEADS;
    int i0 = blockIdx.x * 128;
    int tid = threadIdx.x, lane = tid & 31, warp = tid >> 5;
    int wm = (warp >> 2) * 64, wn = (warp & 3) * 16;

    const __nv_bfloat16* Pb = P + ((size_t)bh << 20);
    const __nv_bfloat16* Vb = qkv + (size_t)b * SEQ * H3 + 2 * CDIM + h * HD;
    uint32_t psb = cvta_smem(Ps), vsb = cvta_smem(Vs);

    float acc[4][2][4];
    #pragma unroll
    for (int i = 0; i < 4; i++)
        #pragma unroll
        for (int j = 0; j < 2; j++)
            #pragma unroll
            for (int k = 0; k < 4; k++) acc[i][j][k] = 0.0f;

    for (int jt = 0; jt < 8; jt++) {
        int j0 = jt * 128;
        // P tile: 128x128 = 2048 chunks -> 8/thread
        #pragma unroll
        for (int t = 0; t < 8; t++) {
            int idx = tid + t * 256;
            int r = idx >> 4, c = idx & 15;
            uint32_t off = r * 256 + ((c ^ (r & 7)) * 16);
            cp16(psb + off, Pb + (size_t)(i0 + r) * SEQ + j0 + c * 8);
        }
        // V tile: 128x64 = 1024 chunks -> 4/thread
        #pragma unroll
        for (int t = 0; t < 4; t++) {
            int idx = tid + t * 256;
            int r = idx >> 3, c = idx & 7;
            uint32_t off = r * 128 + ((c ^ (r & 7)) * 16);
            cp16(vsb + off, Vb + (size_t)(j0 + r) * H3 + c * 8);
        }
        cp_commit();
        cp_wait0();
        __syncthreads();

        #pragma unroll
        for (int s = 0; s < 8; s++) {
            uint32_t af[4][4];
            #pragma unroll
            for (int mi = 0; mi < 4; mi++) {
                int r = wm + mi * 16 + (lane & 15);
                int ch = s * 2 + (lane >> 4);
                ldsm_x4(af[mi][0], af[mi][1], af[mi][2], af[mi][3],
                        psb + r * 256 + ((ch ^ (r & 7)) * 16));
            }
            uint32_t bf[2][2];
            {
                int r = s * 16 + (lane & 15);
                int ch = wn / 8 + (lane >> 4);
                uint32_t t0, t1, t2, t3;
                ldsm_x4_t(t0, t1, t2, t3, vsb + r * 128 + ((ch ^ (r & 7)) * 16));
                bf[0][0] = t0; bf[0][1] = t1; bf[1][0] = t2; bf[1][1] = t3;
            }
            #pragma unroll
            for (int mi = 0; mi < 4; mi++)
                #pragma unroll
                for (int ni = 0; ni < 2; ni++)
                    mma_bf16(acc[mi][ni], af[mi], bf[ni]);
        }
        __syncthreads();
    }

    #pragma unroll
    for (int mi = 0; mi < 4; mi++)
        #pragma unroll
        for (int ni = 0; ni < 2; ni++)
            #pragma unroll
            for (int hh = 0; hh < 2; hh++) {
                int row = i0 + wm + mi * 16 + (lane >> 2) + hh * 8;
                int col = wn + ni * 8 + (lane & 3) * 2;
                size_t m = (size_t)b * SEQ + row;
                float2 v = make_float2(acc[mi][ni][hh * 2], acc[mi][ni][hh * 2 + 1]);
                *(__nv_bfloat162*)(attn_out + m * CDIM + h * HD + col) =
                    __float22bfloat162_rn(v);
            }
}

// ---------------- launch ----------------
extern "C" void kernel_launch(void* const* d_in, const int* in_sizes, int n_in,
                              void* d_out, int out_size) {
    const float* x      = (const float*)d_in[0];
    const float* ln1_g  = (const float*)d_in[1];
    const float* ln1_b  = (const float*)d_in[2];
    const float* w_qkv  = (const float*)d_in[3];
    const float* b_qkv  = (const float*)d_in[4];
    const float* w_proj = (const float*)d_in[5];
    const float* b_proj = (const float*)d_in[6];
    const float* gamma1 = (const float*)d_in[7];
    const float* ln2_g  = (const float*)d_in[8];
    const float* ln2_b  = (const float*)d_in[9];
    const float* w_fc1  = (const float*)d_in[10];
    const float* b_fc1  = (const float*)d_in[11];
    const float* w_fc2  = (const float*)d_in[12];
    const float* b_fc2  = (const float*)d_in[13];
    const float* gamma2 = (const float*)d_in[14];
    float* out = (float*)d_out;

    __nv_bfloat16 *ln, *qkv, *p, *attn, *h, *wqkv, *wproj, *wfc1, *wfc2;
    float *sc, *x1;
    cudaGetSymbolAddress((void**)&ln,    g_ln_bf);
    cudaGetSymbolAddress((void**)&qkv,   g_qkv_bf);
    cudaGetSymbolAddress((void**)&sc,    g_scores);
    cudaGetSymbolAddress((void**)&p,     g_p);
    cudaGetSymbolAddress((void**)&attn,  g_attn_bf);
    cudaGetSymbolAddress((void**)&x1,    g_x1);
    cudaGetSymbolAddress((void**)&h,     g_h_bf);
    cudaGetSymbolAddress((void**)&wqkv,  g_wqkv_bf);
    cudaGetSymbolAddress((void**)&wproj, g_wproj_bf);
    cudaGetSymbolAddress((void**)&wfc1,  g_wfc1_bf);
    cudaGetSymbolAddress((void**)&wfc2,  g_wfc2_bf);

    // weight conversions
    f2bf_kernel<<<(CDIM * H3 / 4 + 255) / 256, 256>>>(w_qkv, wqkv, CDIM * H3);
    f2bf_kernel<<<(CDIM * CDIM / 4 + 255) / 256, 256>>>(w_proj, wproj, CDIM * CDIM);
    f2bf_kernel<<<(CDIM * HID / 4 + 255) / 256, 256>>>(w_fc1, wfc1, CDIM * HID);
    f2bf_kernel<<<(HID * CDIM / 4 + 255) / 256, 256>>>(w_fc2, wfc2, HID * CDIM);

    // 1) ln1
    ln_kernel<<<MROWS, 256>>>(x, ln1_g, ln1_b, ln);
    // 2) qkv = ln @ w_qkv + b_qkv  (bf16 out)
    gemm_bf16<0><<<dim3(H3 / 128, MROWS / 128), 256>>>(ln, wqkv, b_qkv, nullptr, nullptr, qkv, MROWS, H3, CDIM);
    // 3) scores (fp32)
    attn_scores_kernel<<<dim3(8, 8, BHEAD), 256>>>(qkv, sc);
    // 4) softmax -> bf16 P
    softmax_kernel<<<BHEAD * SEQ, 256>>>(sc, p);
    // 5) O = P @ V (bf16 out)
    attn_av_kernel<<<dim3(8, BHEAD), 256>>>(p, qkv, attn);
    // 6) x1 = x + gamma1 * (attn @ w_proj + b_proj)  (fp32 out)
    gemm_bf16<1><<<dim3(CDIM / 128, MROWS / 128), 256>>>(attn, wproj, b_proj, x, gamma1, x1, MROWS, CDIM, CDIM);
    // 7) ln2
    ln_kernel<<<MROWS, 256>>>(x1, ln2_g, ln2_b, ln);
    // 8) h = gelu(ln @ w_fc1 + b_fc1)  (bf16 out)
    gemm_bf16<2><<<dim3(HID / 128, MROWS / 128), 256>>>(ln, wfc1, b_fc1, nullptr, nullptr, h, MROWS, HID, CDIM);
    // 9) out = x1 + gamma2 * (h @ w_fc2 + b_fc2)  (fp32 out)
    gemm_bf16<1><<<dim3(CDIM / 128, MROWS / 128), 256>>>(h, wfc2, b_fc2, x1, gamma2, out, MROWS, CDIM, HID);
}

// round 4
// speedup vs baseline: 7.8558x; 1.3320x over previous
#include <cuda_runtime.h>
#include <cuda_bf16.h>
#include <math.h>
#include <stdint.h>

// Problem constants
#define BATCH 8
#define SEQ   1024
#define CDIM  768
#define HEADS 12
#define HD    64
#define H3    2304
#define HID   3072
#define MROWS (BATCH*SEQ)        // 8192
#define BHEAD (BATCH*HEADS)      // 96
#define LN_EPS 1e-3f

// ---------------- static scratch ----------------
__device__ __nv_bfloat16 g_ln_bf[MROWS * CDIM];
__device__ __nv_bfloat16 g_qkv_bf[MROWS * H3];
__device__ __nv_bfloat16 g_attn_bf[MROWS * CDIM];
__device__ float         g_x1[MROWS * CDIM];
__device__ __nv_bfloat16 g_h_bf[MROWS * HID];
__device__ __nv_bfloat16 g_wqkv_bf[CDIM * H3];
__device__ __nv_bfloat16 g_wproj_bf[CDIM * CDIM];
__device__ __nv_bfloat16 g_wfc1_bf[CDIM * HID];
__device__ __nv_bfloat16 g_wfc2_bf[HID * CDIM];

// ---------------- PTX helpers ----------------
__device__ __forceinline__ uint32_t cvta_smem(const void* p) {
    return (uint32_t)__cvta_generic_to_shared(p);
}
__device__ __forceinline__ void ldsm_x4(uint32_t& r0, uint32_t& r1, uint32_t& r2, uint32_t& r3, uint32_t a) {
    asm volatile("ldmatrix.sync.aligned.m8n8.x4.shared.b16 {%0,%1,%2,%3},[%4];"
                 : "=r"(r0), "=r"(r1), "=r"(r2), "=r"(r3) : "r"(a));
}
__device__ __forceinline__ void ldsm_x4_t(uint32_t& r0, uint32_t& r1, uint32_t& r2, uint32_t& r3, uint32_t a) {
    asm volatile("ldmatrix.sync.aligned.m8n8.x4.trans.shared.b16 {%0,%1,%2,%3},[%4];"
                 : "=r"(r0), "=r"(r1), "=r"(r2), "=r"(r3) : "r"(a));
}
__device__ __forceinline__ void mma_bf16(float* c, const uint32_t* a, const uint32_t* b) {
    asm volatile("mma.sync.aligned.m16n8k16.row.col.f32.bf16.bf16.f32 "
                 "{%0,%1,%2,%3},{%4,%5,%6,%7},{%8,%9},{%0,%1,%2,%3};"
                 : "+f"(c[0]), "+f"(c[1]), "+f"(c[2]), "+f"(c[3])
                 : "r"(a[0]), "r"(a[1]), "r"(a[2]), "r"(a[3]), "r"(b[0]), "r"(b[1]));
}
__device__ __forceinline__ void cp16(uint32_t saddr, const void* g) {
    asm volatile("cp.async.cg.shared.global [%0],[%1],16;" :: "r"(saddr), "l"(g));
}
__device__ __forceinline__ void cp_commit() { asm volatile("cp.async.commit_group;"); }
__device__ __forceinline__ void cp_wait0()  { asm volatile("cp.async.wait_group 0;"); }
__device__ __forceinline__ void cp_wait1()  { asm volatile("cp.async.wait_group 1;"); }
__device__ __forceinline__ uint32_t pkbf(float x, float y) {
    __nv_bfloat162 t = __float22bfloat162_rn(make_float2(x, y));
    return *(uint32_t*)&t;
}

// ---------------- fp32 -> bf16 convert ----------------
__global__ void f2bf_kernel(const float* __restrict__ in, __nv_bfloat16* __restrict__ out, int n) {
    int i = (blockIdx.x * blockDim.x + threadIdx.x) * 4;
    if (i < n) {
        float4 v = *(const float4*)(in + i);
        __nv_bfloat162* o = (__nv_bfloat162*)(out + i);
        o[0] = __float22bfloat162_rn(make_float2(v.x, v.y));
        o[1] = __float22bfloat162_rn(make_float2(v.z, v.w));
    }
}

// ---------------- reductions ----------------
__device__ __forceinline__ float block_reduce_sum(float v, float* sh) {
    __syncthreads();
    #pragma unroll
    for (int o = 16; o > 0; o >>= 1) v += __shfl_xor_sync(0xffffffffu, v, o);
    int warp = threadIdx.x >> 5, lane = threadIdx.x & 31;
    if (lane == 0) sh[warp] = v;
    __syncthreads();
    if (warp == 0) {
        v = (lane < (blockDim.x >> 5)) ? sh[lane] : 0.0f;
        #pragma unroll
        for (int o = 4; o > 0; o >>= 1) v += __shfl_xor_sync(0xffffffffu, v, o);
        if (lane == 0) sh[0] = v;
    }
    __syncthreads();
    return sh[0];
}

// ---------------- LayerNorm (fp32 in -> bf16 out) ----------------
__global__ void ln_kernel(const float* __restrict__ x, const float* __restrict__ g,
                          const float* __restrict__ b, __nv_bfloat16* __restrict__ out) {
    __shared__ float sh[32];
    int row = blockIdx.x;
    int t = threadIdx.x;
    const float* xr = x + (size_t)row * CDIM;
    float v0 = xr[t], v1 = xr[t + 256], v2 = xr[t + 512];
    float s = block_reduce_sum(v0 + v1 + v2, sh);
    float mu = s * (1.0f / CDIM);
    float d0 = v0 - mu, d1 = v1 - mu, d2 = v2 - mu;
    float s2 = block_reduce_sum(d0 * d0 + d1 * d1 + d2 * d2, sh);
    float rstd = rsqrtf(s2 * (1.0f / CDIM) + LN_EPS);
    __nv_bfloat16* outr = out + (size_t)row * CDIM;
    outr[t]       = __float2bfloat16(d0 * rstd * g[t]       + b[t]);
    outr[t + 256] = __float2bfloat16(d1 * rstd * g[t + 256] + b[t + 256]);
    outr[t + 512] = __float2bfloat16(d2 * rstd * g[t + 512] + b[t + 512]);
}

// ---------------- bf16 GEMM 128x128x32, 256 threads, 8 warps (2x4) ----------------
template<int MODE>
__global__ __launch_bounds__(256) void gemm_bf16(
    const __nv_bfloat16* __restrict__ A, const __nv_bfloat16* __restrict__ B,
    const float* __restrict__ bias, const float* __restrict__ res,
    const float* __restrict__ gamma, void* __restrict__ Cout,
    int M, int N, int K)
{
    __shared__ __align__(16) __nv_bfloat16 As[2][128 * 32];
    __shared__ __align__(16) __nv_bfloat16 Bs[2][32 * 128];

    int tid = threadIdx.x, lane = tid & 31, warp = tid >> 5;
    int wm = (warp >> 2) * 64, wn = (warp & 3) * 32;
    int bx = blockIdx.x, by = blockIdx.y;

    int a_row = tid >> 2, a_c = tid & 3;
    int b_row = tid >> 4, b_c = tid & 15;
    const __nv_bfloat16* Ag = A + (size_t)(by * 128 + a_row) * K + a_c * 8;
    const __nv_bfloat16* Ag2 = Ag + (size_t)64 * K;
    const __nv_bfloat16* Bg = B + (size_t)b_row * N + bx * 128 + b_c * 8;
    const __nv_bfloat16* Bg2 = Bg + (size_t)16 * N;

    uint32_t asb[2], bsb[2];
    asb[0] = cvta_smem(As[0]); asb[1] = cvta_smem(As[1]);
    bsb[0] = cvta_smem(Bs[0]); bsb[1] = cvta_smem(Bs[1]);
    uint32_t a_off  = a_row * 64 + ((a_c ^ ((a_row >> 1) & 3)) * 16);
    uint32_t a_off2 = (a_row + 64) * 64 + ((a_c ^ (((a_row + 64) >> 1) & 3)) * 16);
    uint32_t b_off  = b_row * 256 + ((b_c ^ (b_row & 7)) * 16);
    uint32_t b_off2 = (b_row + 16) * 256 + ((b_c ^ ((b_row + 16) & 7)) * 16);

    float acc[4][4][4];
    #pragma unroll
    for (int i = 0; i < 4; i++)
        #pragma unroll
        for (int j = 0; j < 4; j++)
            #pragma unroll
            for (int k = 0; k < 4; k++) acc[i][j][k] = 0.0f;

    int KB = K >> 5;
    cp16(asb[0] + a_off,  Ag);
    cp16(asb[0] + a_off2, Ag2);
    cp16(bsb[0] + b_off,  Bg);
    cp16(bsb[0] + b_off2, Bg2);
    cp_commit();

    uint32_t a_frag_off[4][2], b_frag_off[2][2];
    #pragma unroll
    for (int mi = 0; mi < 4; mi++) {
        int r = wm + mi * 16 + (lane & 15);
        #pragma unroll
        for (int k16 = 0; k16 < 2; k16++) {
            int ch = k16 * 2 + (lane >> 4);
            a_frag_off[mi][k16] = r * 64 + ((ch ^ ((r >> 1) & 3)) * 16);
        }
    }
    #pragma unroll
    for (int nh = 0; nh < 2; nh++) {
        #pragma unroll
        for (int k16 = 0; k16 < 2; k16++) {
            int r = k16 * 16 + (lane & 15);
            int ch = (wn >> 3) + nh * 2 + (lane >> 4);
            b_frag_off[nh][k16] = r * 256 + ((ch ^ (r & 7)) * 16);
        }
    }

    for (int kb = 0; kb < KB; kb++) {
        if (kb + 1 < KB) {
            int st = (kb + 1) & 1;
            size_t ka = (size_t)(kb + 1) * 32;
            cp16(asb[st] + a_off,  Ag + ka);
            cp16(asb[st] + a_off2, Ag2 + ka);
            cp16(bsb[st] + b_off,  Bg + ka * N);
            cp16(bsb[st] + b_off2, Bg2 + ka * N);
            cp_commit();
            cp_wait1();
        } else {
            cp_wait0();
        }
        __syncthreads();
        int st = kb & 1;
        #pragma unroll
        for (int k16 = 0; k16 < 2; k16++) {
            uint32_t af[4][4];
            #pragma unroll
            for (int mi = 0; mi < 4; mi++)
                ldsm_x4(af[mi][0], af[mi][1], af[mi][2], af[mi][3], asb[st] + a_frag_off[mi][k16]);
            uint32_t bf[4][2];
            #pragma unroll
            for (int nh = 0; nh < 2; nh++) {
                uint32_t t0, t1, t2, t3;
                ldsm_x4_t(t0, t1, t2, t3, bsb[st] + b_frag_off[nh][k16]);
                bf[nh * 2][0] = t0; bf[nh * 2][1] = t1;
                bf[nh * 2 + 1][0] = t2; bf[nh * 2 + 1][1] = t3;
            }
            #pragma unroll
            for (int mi = 0; mi < 4; mi++)
                #pragma unroll
                for (int ni = 0; ni < 4; ni++)
                    mma_bf16(acc[mi][ni], af[mi], bf[ni]);
        }
        __syncthreads();
    }

    #pragma unroll
    for (int mi = 0; mi < 4; mi++) {
        #pragma unroll
        for (int ni = 0; ni < 4; ni++) {
            #pragma unroll
            for (int hh = 0; hh < 2; hh++) {
                int row = by * 128 + wm + mi * 16 + (lane >> 2) + hh * 8;
                int col = bx * 128 + wn + ni * 8 + (lane & 3) * 2;
                float vx = acc[mi][ni][hh * 2]     + bias[col];
                float vy = acc[mi][ni][hh * 2 + 1] + bias[col + 1];
                size_t off = (size_t)row * N + col;
                if (MODE == 1) {
                    float* C = (float*)Cout;
                    float2 r = *(const float2*)(res + off);
                    float2 o;
                    o.x = r.x + gamma[col]     * vx;
                    o.y = r.y + gamma[col + 1] * vy;
                    *(float2*)(C + off) = o;
                } else {
                    if (MODE == 2) {
                        vx = 0.5f * vx * (1.0f + erff(vx * 0.70710678118654752f));
                        vy = 0.5f * vy * (1.0f + erff(vy * 0.70710678118654752f));
                    }
                    __nv_bfloat16* C = (__nv_bfloat16*)Cout;
                    *(__nv_bfloat162*)(C + off) = __float22bfloat162_rn(make_float2(vx, vy));
                }
            }
        }
    }
}

// ---------------- fused flash attention ----------------
// grid (8 itiles, 96 bh), 256 threads (8 warps). Warp w owns rows wm = w*16.
// smem: Q[128x64] @0 (16KB); K/V double buffered: K0@16K V0@32K K1@48K V1@64K.
#define FA_SMEM (5 * 16384)

__global__ __launch_bounds__(256) void flash_attn_kernel(const __nv_bfloat16* __restrict__ qkv,
                                                         __nv_bfloat16* __restrict__ attn_out) {
    extern __shared__ char fsm[];
    uint32_t sb = cvta_smem(fsm);
    int bh = blockIdx.y;
    int b = bh / HEADS, h = bh % HEADS;
    int i0 = blockIdx.x * 128;
    int tid = threadIdx.x, lane = tid & 31, w = tid >> 5;
    int wm = w * 16;

    const __nv_bfloat16* Qb = qkv + (size_t)b * SEQ * H3 + h * HD;
    const __nv_bfloat16* Kb = Qb + CDIM;
    const __nv_bfloat16* Vb = Qb + 2 * CDIM;

    // G0: Q + K0 + V0
    #pragma unroll
    for (int t = 0; t < 4; t++) {
        int idx = tid + t * 256;
        int r = idx >> 3, c = idx & 7;
        uint32_t off = r * 128 + ((c ^ (r & 7)) * 16);
        cp16(sb + off,         Qb + (size_t)(i0 + r) * H3 + c * 8);
        cp16(sb + 16384 + off, Kb + (size_t)r * H3 + c * 8);
        cp16(sb + 32768 + off, Vb + (size_t)r * H3 + c * 8);
    }
    cp_commit();
    // G1: K1 + V1
    #pragma unroll
    for (int t = 0; t < 4; t++) {
        int idx = tid + t * 256;
        int r = idx >> 3, c = idx & 7;
        uint32_t off = r * 128 + ((c ^ (r & 7)) * 16);
        cp16(sb + 49152 + off, Kb + (size_t)(128 + r) * H3 + c * 8);
        cp16(sb + 65536 + off, Vb + (size_t)(128 + r) * H3 + c * 8);
    }
    cp_commit();

    // wait Q (G0 will complete with first loop wait; need Q before frag load)
    cp_wait1();
    __syncthreads();

    // Q fragments (held in registers for whole kernel)
    uint32_t aq[4][4];
    #pragma unroll
    for (int k16 = 0; k16 < 4; k16++) {
        int r = wm + (lane & 15);
        int ch = k16 * 2 + (lane >> 4);
        ldsm_x4(aq[k16][0], aq[k16][1], aq[k16][2], aq[k16][3],
                sb + r * 128 + ((ch ^ (r & 7)) * 16));
    }

    float m0 = -1e30f, m1 = -1e30f, l0 = 0.0f, l1 = 0.0f;
    float acc_o[8][4];
    #pragma unroll
    for (int i = 0; i < 8; i++)
        #pragma unroll
        for (int j = 0; j < 4; j++) acc_o[i][j] = 0.0f;

    for (int jt = 0; jt < 8; jt++) {
        if (jt < 7) cp_wait1(); else cp_wait0();
        __syncthreads();
        uint32_t ksb = sb + 16384 + (jt & 1) * 32768;
        uint32_t vsb = sb + 32768 + (jt & 1) * 32768;

        // S = Q @ K^T (16 x 128 per warp)
        float s[16][4];
        #pragma unroll
        for (int n = 0; n < 16; n++)
            #pragma unroll
            for (int j = 0; j < 4; j++) s[n][j] = 0.0f;
        #pragma unroll
        for (int k16 = 0; k16 < 4; k16++) {
            #pragma unroll
            for (int nh = 0; nh < 8; nh++) {
                int r = nh * 16 + (lane & 15);
                int ch = k16 * 2 + (lane >> 4);
                uint32_t t0, t1, t2, t3;
                ldsm_x4(t0, t1, t2, t3, ksb + r * 128 + ((ch ^ (r & 7)) * 16));
                uint32_t b0[2] = {t0, t2}, b1[2] = {t1, t3};
                mma_bf16(s[nh * 2], aq[k16], b0);
                mma_bf16(s[nh * 2 + 1], aq[k16], b1);
            }
        }

        // scale + online softmax stats
        float mx0 = -1e30f, mx1 = -1e30f;
        #pragma unroll
        for (int n = 0; n < 16; n++) {
            s[n][0] *= 0.125f; s[n][1] *= 0.125f; s[n][2] *= 0.125f; s[n][3] *= 0.125f;
            mx0 = fmaxf(mx0, fmaxf(s[n][0], s[n][1]));
            mx1 = fmaxf(mx1, fmaxf(s[n][2], s[n][3]));
        }
        mx0 = fmaxf(mx0, __shfl_xor_sync(0xffffffffu, mx0, 1));
        mx0 = fmaxf(mx0, __shfl_xor_sync(0xffffffffu, mx0, 2));
        mx1 = fmaxf(mx1, __shfl_xor_sync(0xffffffffu, mx1, 1));
        mx1 = fmaxf(mx1, __shfl_xor_sync(0xffffffffu, mx1, 2));
        float mn0 = fmaxf(m0, mx0), mn1 = fmaxf(m1, mx1);
        float c0 = __expf(m0 - mn0), c1 = __expf(m1 - mn1);
        float sum0 = 0.0f, sum1 = 0.0f;
        #pragma unroll
        for (int n = 0; n < 16; n++) {
            s[n][0] = __expf(s[n][0] - mn0); s[n][1] = __expf(s[n][1] - mn0);
            s[n][2] = __expf(s[n][2] - mn1); s[n][3] = __expf(s[n][3] - mn1);
            sum0 += s[n][0] + s[n][1];
            sum1 += s[n][2] + s[n][3];
        }
        sum0 += __shfl_xor_sync(0xffffffffu, sum0, 1);
        sum0 += __shfl_xor_sync(0xffffffffu, sum0, 2);
        sum1 += __shfl_xor_sync(0xffffffffu, sum1, 1);
        sum1 += __shfl_xor_sync(0xffffffffu, sum1, 2);
        l0 = l0 * c0 + sum0; l1 = l1 * c1 + sum1;
        m0 = mn0; m1 = mn1;
        #pragma unroll
        for (int i = 0; i < 8; i++) {
            acc_o[i][0] *= c0; acc_o[i][1] *= c0;
            acc_o[i][2] *= c1; acc_o[i][3] *= c1;
        }

        // pack P -> bf16 A fragments (k = 128 over j dim)
        uint32_t pa[8][4];
        #pragma unroll
        for (int kc = 0; kc < 8; kc++) {
            pa[kc][0] = pkbf(s[2 * kc][0], s[2 * kc][1]);
            pa[kc][1] = pkbf(s[2 * kc][2], s[2 * kc][3]);
            pa[kc][2] = pkbf(s[2 * kc + 1][0], s[2 * kc + 1][1]);
            pa[kc][3] = pkbf(s[2 * kc + 1][2], s[2 * kc + 1][3]);
        }

        // O += P @ V
        #pragma unroll
        for (int kc = 0; kc < 8; kc++) {
            #pragma unroll
            for (int vh = 0; vh < 4; vh++) {
                int r = kc * 16 + (lane & 15);
                int ch = vh * 2 + (lane >> 4);
                uint32_t t0, t1, t2, t3;
                ldsm_x4_t(t0, t1, t2, t3, vsb + r * 128 + ((ch ^ (r & 7)) * 16));
                uint32_t b0[2] = {t0, t1}, b1[2] = {t2, t3};
                mma_bf16(acc_o[vh * 2], pa[kc], b0);
                mma_bf16(acc_o[vh * 2 + 1], pa[kc], b1);
            }
        }

        __syncthreads();   // everyone done reading this buffer
        int nj = jt + 2;
        if (nj < 8) {
            uint32_t kdst = sb + 16384 + (nj & 1) * 32768;
            uint32_t vdst = kdst + 16384;
            #pragma unroll
            for (int t = 0; t < 4; t++) {
                int idx = tid + t * 256;
                int r = idx >> 3, c = idx & 7;
                uint32_t off = r * 128 + ((c ^ (r & 7)) * 16);
                cp16(kdst + off, Kb + (size_t)(nj * 128 + r) * H3 + c * 8);
                cp16(vdst + off, Vb + (size_t)(nj * 128 + r) * H3 + c * 8);
            }
            cp_commit();
        }
    }

    // normalize + write out
    float inv0 = 1.0f / l0, inv1 = 1.0f / l1;
    int r0 = i0 + wm + (lane >> 2);
    size_t base0 = ((size_t)b * SEQ + r0) * CDIM + h * HD;
    size_t base1 = base0 + 8 * CDIM;
    #pragma unroll
    for (int nt = 0; nt < 8; nt++) {
        int col = nt * 8 + (lane & 3) * 2;
        *(__nv_bfloat162*)(attn_out + base0 + col) =
            __float22bfloat162_rn(make_float2(acc_o[nt][0] * inv0, acc_o[nt][1] * inv0));
        *(__nv_bfloat162*)(attn_out + base1 + col) =
            __float22bfloat162_rn(make_float2(acc_o[nt][2] * inv1, acc_o[nt][3] * inv1));
    }
}

// ---------------- launch ----------------
extern "C" void kernel_launch(void* const* d_in, const int* in_sizes, int n_in,
                              void* d_out, int out_size) {
    const float* x      = (const float*)d_in[0];
    const float* ln1_g  = (const float*)d_in[1];
    const float* ln1_b  = (const float*)d_in[2];
    const float* w_qkv  = (const float*)d_in[3];
    const float* b_qkv  = (const float*)d_in[4];
    const float* w_proj = (const float*)d_in[5];
    const float* b_proj = (const float*)d_in[6];
    const float* gamma1 = (const float*)d_in[7];
    const float* ln2_g  = (const float*)d_in[8];
    const float* ln2_b  = (const float*)d_in[9];
    const float* w_fc1  = (const float*)d_in[10];
    const float* b_fc1  = (const float*)d_in[11];
    const float* w_fc2  = (const float*)d_in[12];
    const float* b_fc2  = (const float*)d_in[13];
    const float* gamma2 = (const float*)d_in[14];
    float* out = (float*)d_out;

    __nv_bfloat16 *ln, *qkv, *attn, *h, *wqkv, *wproj, *wfc1, *wfc2;
    float *x1;
    cudaGetSymbolAddress((void**)&ln,    g_ln_bf);
    cudaGetSymbolAddress((void**)&qkv,   g_qkv_bf);
    cudaGetSymbolAddress((void**)&attn,  g_attn_bf);
    cudaGetSymbolAddress((void**)&x1,    g_x1);
    cudaGetSymbolAddress((void**)&h,     g_h_bf);
    cudaGetSymbolAddress((void**)&wqkv,  g_wqkv_bf);
    cudaGetSymbolAddress((void**)&wproj, g_wproj_bf);
    cudaGetSymbolAddress((void**)&wfc1,  g_wfc1_bf);
    cudaGetSymbolAddress((void**)&wfc2,  g_wfc2_bf);

    cudaFuncSetAttribute(flash_attn_kernel, cudaFuncAttributeMaxDynamicSharedMemorySize, FA_SMEM);

    // weight conversions
    f2bf_kernel<<<(CDIM * H3 / 4 + 255) / 256, 256>>>(w_qkv, wqkv, CDIM * H3);
    f2bf_kernel<<<(CDIM * CDIM / 4 + 255) / 256, 256>>>(w_proj, wproj, CDIM * CDIM);
    f2bf_kernel<<<(CDIM * HID / 4 + 255) / 256, 256>>>(w_fc1, wfc1, CDIM * HID);
    f2bf_kernel<<<(HID * CDIM / 4 + 255) / 256, 256>>>(w_fc2, wfc2, HID * CDIM);

    // 1) ln1
    ln_kernel<<<MROWS, 256>>>(x, ln1_g, ln1_b, ln);
    // 2) qkv = ln @ w_qkv + b_qkv  (bf16 out)
    gemm_bf16<0><<<dim3(H3 / 128, MROWS / 128), 256>>>(ln, wqkv, b_qkv, nullptr, nullptr, qkv, MROWS, H3, CDIM);
    // 3) fused attention -> attn (bf16)
    flash_attn_kernel<<<dim3(8, BHEAD), 256, FA_SMEM>>>(qkv, attn);
    // 4) x1 = x + gamma1 * (attn @ w_proj + b_proj)  (fp32 out)
    gemm_bf16<1><<<dim3(CDIM / 128, MROWS / 128), 256>>>(attn, wproj, b_proj, x, gamma1, x1, MROWS, CDIM, CDIM);
    // 5) ln2
    ln_kernel<<<MROWS, 256>>>(x1, ln2_g, ln2_b, ln);
    // 6) h = gelu(ln @ w_fc1 + b_fc1)  (bf16 out)
    gemm_bf16<2><<<dim3(HID / 128, MROWS / 128), 256>>>(ln, wfc1, b_fc1, nullptr, nullptr, h, MROWS, HID, CDIM);
    // 7) out = x1 + gamma2 * (h @ w_fc2 + b_fc2)  (fp32 out)
    gemm_bf16<1><<<dim3(CDIM / 128, MROWS / 128), 256>>>(h, wfc2, b_fc2, x1, gamma2, out, MROWS, CDIM, HID);
}

// round 5
// speedup vs baseline: 8.6341x; 1.0991x over previous
#include <cuda_runtime.h>
#include <cuda_bf16.h>
#include <math.h>
#include <stdint.h>

// Problem constants
#define BATCH 8
#define SEQ   1024
#define CDIM  768
#define HEADS 12
#define HD    64
#define H3    2304
#define HID   3072
#define MROWS (BATCH*SEQ)        // 8192
#define BHEAD (BATCH*HEADS)      // 96
#define LN_EPS 1e-3f

// ---------------- static scratch ----------------
__device__ __nv_bfloat16 g_ln_bf[MROWS * CDIM];
__device__ __nv_bfloat16 g_qkv_bf[MROWS * H3];
__device__ __nv_bfloat16 g_attn_bf[MROWS * CDIM];
__device__ float         g_x1[MROWS * CDIM];
__device__ __nv_bfloat16 g_h_bf[MROWS * HID];
__device__ __nv_bfloat16 g_wqkv_bf[CDIM * H3];
__device__ __nv_bfloat16 g_wproj_bf[CDIM * CDIM];
__device__ __nv_bfloat16 g_wfc1_bf[CDIM * HID];
__device__ __nv_bfloat16 g_wfc2_bf[HID * CDIM];

// ---------------- PTX helpers ----------------
__device__ __forceinline__ uint32_t cvta_smem(const void* p) {
    return (uint32_t)__cvta_generic_to_shared(p);
}
__device__ __forceinline__ void ldsm_x4(uint32_t& r0, uint32_t& r1, uint32_t& r2, uint32_t& r3, uint32_t a) {
    asm volatile("ldmatrix.sync.aligned.m8n8.x4.shared.b16 {%0,%1,%2,%3},[%4];"
                 : "=r"(r0), "=r"(r1), "=r"(r2), "=r"(r3) : "r"(a));
}
__device__ __forceinline__ void ldsm_x4_t(uint32_t& r0, uint32_t& r1, uint32_t& r2, uint32_t& r3, uint32_t a) {
    asm volatile("ldmatrix.sync.aligned.m8n8.x4.trans.shared.b16 {%0,%1,%2,%3},[%4];"
                 : "=r"(r0), "=r"(r1), "=r"(r2), "=r"(r3) : "r"(a));
}
__device__ __forceinline__ void mma_bf16(float* c, const uint32_t* a, const uint32_t* b) {
    asm volatile("mma.sync.aligned.m16n8k16.row.col.f32.bf16.bf16.f32 "
                 "{%0,%1,%2,%3},{%4,%5,%6,%7},{%8,%9},{%0,%1,%2,%3};"
                 : "+f"(c[0]), "+f"(c[1]), "+f"(c[2]), "+f"(c[3])
                 : "r"(a[0]), "r"(a[1]), "r"(a[2]), "r"(a[3]), "r"(b[0]), "r"(b[1]));
}
__device__ __forceinline__ void cp16(uint32_t saddr, const void* g) {
    asm volatile("cp.async.cg.shared.global [%0],[%1],16;" :: "r"(saddr), "l"(g));
}
__device__ __forceinline__ void cp_commit() { asm volatile("cp.async.commit_group;"); }
__device__ __forceinline__ void cp_wait0()  { asm volatile("cp.async.wait_group 0;"); }
__device__ __forceinline__ void cp_wait1()  { asm volatile("cp.async.wait_group 1;"); }
__device__ __forceinline__ uint32_t pkbf(float x, float y) {
    __nv_bfloat162 t = __float22bfloat162_rn(make_float2(x, y));
    return *(uint32_t*)&t;
}

// ---------------- merged fp32 -> bf16 weight convert ----------------
#define N0 (CDIM*H3)
#define N1 (CDIM*CDIM)
#define N2 (CDIM*HID)
#define N3 (HID*CDIM)
__global__ void f2bf4_kernel(const float* __restrict__ w0, const float* __restrict__ w1,
                             const float* __restrict__ w2, const float* __restrict__ w3,
                             __nv_bfloat16* __restrict__ o0, __nv_bfloat16* __restrict__ o1,
                             __nv_bfloat16* __restrict__ o2, __nv_bfloat16* __restrict__ o3) {
    int i = (blockIdx.x * blockDim.x + threadIdx.x) * 4;
    const float* src; __nv_bfloat16* dst; int off;
    if (i < N0)                { src = w0; dst = o0; off = i; }
    else if (i < N0+N1)        { src = w1; dst = o1; off = i - N0; }
    else if (i < N0+N1+N2)     { src = w2; dst = o2; off = i - N0 - N1; }
    else                       { src = w3; dst = o3; off = i - N0 - N1 - N2; }
    float4 v = *(const float4*)(src + off);
    __nv_bfloat162* o = (__nv_bfloat162*)(dst + off);
    o[0] = __float22bfloat162_rn(make_float2(v.x, v.y));
    o[1] = __float22bfloat162_rn(make_float2(v.z, v.w));
}

// ---------------- reductions ----------------
__device__ __forceinline__ float block_reduce_sum(float v, float* sh) {
    __syncthreads();
    #pragma unroll
    for (int o = 16; o > 0; o >>= 1) v += __shfl_xor_sync(0xffffffffu, v, o);
    int warp = threadIdx.x >> 5, lane = threadIdx.x & 31;
    if (lane == 0) sh[warp] = v;
    __syncthreads();
    if (warp == 0) {
        v = (lane < (blockDim.x >> 5)) ? sh[lane] : 0.0f;
        #pragma unroll
        for (int o = 4; o > 0; o >>= 1) v += __shfl_xor_sync(0xffffffffu, v, o);
        if (lane == 0) sh[0] = v;
    }
    __syncthreads();
    return sh[0];
}

// ---------------- LayerNorm (fp32 in -> bf16 out) ----------------
__global__ void ln_kernel(const float* __restrict__ x, const float* __restrict__ g,
                          const float* __restrict__ b, __nv_bfloat16* __restrict__ out) {
    __shared__ float sh[32];
    int row = blockIdx.x;
    int t = threadIdx.x;
    const float* xr = x + (size_t)row * CDIM;
    float v0 = xr[t], v1 = xr[t + 256], v2 = xr[t + 512];
    float s = block_reduce_sum(v0 + v1 + v2, sh);
    float mu = s * (1.0f / CDIM);
    float d0 = v0 - mu, d1 = v1 - mu, d2 = v2 - mu;
    float s2 = block_reduce_sum(d0 * d0 + d1 * d1 + d2 * d2, sh);
    float rstd = rsqrtf(s2 * (1.0f / CDIM) + LN_EPS);
    __nv_bfloat16* outr = out + (size_t)row * CDIM;
    outr[t]       = __float2bfloat16(d0 * rstd * g[t]       + b[t]);
    outr[t + 256] = __float2bfloat16(d1 * rstd * g[t + 256] + b[t + 256]);
    outr[t + 512] = __float2bfloat16(d2 * rstd * g[t + 512] + b[t + 512]);
}

// ---------------- bf16 GEMM: 128x128 CTA, 4 warps (2x2) of 64x64, K-block 64, 3-stage ----------------
// smem per stage: A 128x64 (16KB) + B 64x128 (16KB) = 32KB; 3 stages = 96KB dynamic.
#define GSTAGE 32768
#define GSMEM  (3 * GSTAGE)

template<int MODE>
__global__ __launch_bounds__(128, 2) void gemm_bf16(
    const __nv_bfloat16* __restrict__ A, const __nv_bfloat16* __restrict__ B,
    const float* __restrict__ bias, const float* __restrict__ res,
    const float* __restrict__ gamma, void* __restrict__ Cout,
    int M, int N, int K)
{
    extern __shared__ char gsm[];
    uint32_t sb = cvta_smem(gsm);

    int tid = threadIdx.x, lane = tid & 31, warp = tid >> 5;
    int wm = (warp >> 1) * 64, wn = (warp & 1) * 64;
    int bx = blockIdx.x, by = blockIdx.y;

    // global load mapping (per thread: 8 A chunks + 8 B chunks per K-block)
    int ar = tid >> 3, ac = tid & 7;          // A: rows ar + t*16, col chunk ac
    int br = tid >> 4, bc = tid & 15;         // B: rows br + t*8,  col chunk bc
    const __nv_bfloat16* Ag = A + (size_t)(by * 128 + ar) * K + ac * 8;
    const __nv_bfloat16* Bg = B + (size_t)br * N + bx * 128 + bc * 8;
    uint32_t a_soff = ar * 128 + ((ac ^ (ar & 7)) * 16);          // +t*16*128
    uint32_t b_soff = 16384 + br * 256 + ((bc ^ (br & 7)) * 16);  // +t*8*256

    float acc[4][8][4];
    #pragma unroll
    for (int i = 0; i < 4; i++)
        #pragma unroll
        for (int j = 0; j < 8; j++)
            #pragma unroll
            for (int k = 0; k < 4; k++) acc[i][j][k] = 0.0f;

    int KB = K >> 6;

    // prologue: stages 0,1
    #pragma unroll
    for (int pb = 0; pb < 2; pb++) {
        uint32_t st = sb + pb * GSTAGE;
        const __nv_bfloat16* Ak = Ag + pb * 64;
        const __nv_bfloat16* Bk = Bg + (size_t)pb * 64 * N;
        #pragma unroll
        for (int t = 0; t < 8; t++) cp16(st + a_soff + t * 2048, Ak + (size_t)t * 16 * K);
        #pragma unroll
        for (int t = 0; t < 8; t++) cp16(st + b_soff + t * 2048, Bk + (size_t)t * 8 * N);
        cp_commit();
    }

    int stage = 0;
    for (int kb = 0; kb < KB; kb++) {
        if (kb + 1 < KB) cp_wait1(); else cp_wait0();
        __syncthreads();
        uint32_t st = sb + stage * GSTAGE;

        #pragma unroll
        for (int k16 = 0; k16 < 4; k16++) {
            uint32_t af[4][4];
            #pragma unroll
            for (int mi = 0; mi < 4; mi++) {
                int r = wm + mi * 16 + (lane & 15);
                int ch = k16 * 2 + (lane >> 4);
                ldsm_x4(af[mi][0], af[mi][1], af[mi][2], af[mi][3],
                        st + r * 128 + ((ch ^ (r & 7)) * 16));
            }
            uint32_t bf[8][2];
            #pragma unroll
            for (int nh = 0; nh < 4; nh++) {
                int r = k16 * 16 + (lane & 15);
                int ch = (wn >> 3) + nh * 2 + (lane >> 4);
                uint32_t t0, t1, t2, t3;
                ldsm_x4_t(t0, t1, t2, t3, st + 16384 + r * 256 + ((ch ^ (r & 7)) * 16));
                bf[nh * 2][0] = t0; bf[nh * 2][1] = t1;
                bf[nh * 2 + 1][0] = t2; bf[nh * 2 + 1][1] = t3;
            }
            #pragma unroll
            for (int mi = 0; mi < 4; mi++)
                #pragma unroll
                for (int ni = 0; ni < 8; ni++)
                    mma_bf16(acc[mi][ni], af[mi], bf[ni]);
        }

        int nb = kb + 2;
        if (nb < KB) {
            uint32_t ld = sb + ((stage + 2) % 3) * GSTAGE;
            const __nv_bfloat16* Ak = Ag + nb * 64;
            const __nv_bfloat16* Bk = Bg + (size_t)nb * 64 * N;
            #pragma unroll
            for (int t = 0; t < 8; t++) cp16(ld + a_soff + t * 2048, Ak + (size_t)t * 16 * K);
            #pragma unroll
            for (int t = 0; t < 8; t++) cp16(ld + b_soff + t * 2048, Bk + (size_t)t * 8 * N);
            cp_commit();
        }
        stage = (stage + 1) % 3;
    }

    // epilogue
    #pragma unroll
    for (int mi = 0; mi < 4; mi++) {
        #pragma unroll
        for (int ni = 0; ni < 8; ni++) {
            #pragma unroll
            for (int hh = 0; hh < 2; hh++) {
                int row = by * 128 + wm + mi * 16 + (lane >> 2) + hh * 8;
                int col = bx * 128 + wn + ni * 8 + (lane & 3) * 2;
                float vx = acc[mi][ni][hh * 2]     + bias[col];
                float vy = acc[mi][ni][hh * 2 + 1] + bias[col + 1];
                size_t off = (size_t)row * N + col;
                if (MODE == 1) {
                    float* C = (float*)Cout;
                    float2 r = *(const float2*)(res + off);
                    float2 o;
                    o.x = r.x + gamma[col]     * vx;
                    o.y = r.y + gamma[col + 1] * vy;
                    *(float2*)(C + off) = o;
                } else {
                    if (MODE == 2) {
                        vx = 0.5f * vx * (1.0f + erff(vx * 0.70710678118654752f));
                        vy = 0.5f * vy * (1.0f + erff(vy * 0.70710678118654752f));
                    }
                    __nv_bfloat16* C = (__nv_bfloat16*)Cout;
                    *(__nv_bfloat162*)(C + off) = __float22bfloat162_rn(make_float2(vx, vy));
                }
            }
        }
    }
}

// ---------------- fused flash attention ----------------
// grid (8 itiles, 96 bh), 256 threads (8 warps). Warp w owns rows wm = w*16.
// smem: Q[128x64] @0 (16KB); K/V double buffered: K0@16K V0@32K K1@48K V1@64K.
#define FA_SMEM (5 * 16384)

__global__ __launch_bounds__(256) void flash_attn_kernel(const __nv_bfloat16* __restrict__ qkv,
                                                         __nv_bfloat16* __restrict__ attn_out) {
    extern __shared__ char fsm[];
    uint32_t sb = cvta_smem(fsm);
    int bh = blockIdx.y;
    int b = bh / HEADS, h = bh % HEADS;
    int i0 = blockIdx.x * 128;
    int tid = threadIdx.x, lane = tid & 31, w = tid >> 5;
    int wm = w * 16;

    const __nv_bfloat16* Qb = qkv + (size_t)b * SEQ * H3 + h * HD;
    const __nv_bfloat16* Kb = Qb + CDIM;
    const __nv_bfloat16* Vb = Qb + 2 * CDIM;

    #pragma unroll
    for (int t = 0; t < 4; t++) {
        int idx = tid + t * 256;
        int r = idx >> 3, c = idx & 7;
        uint32_t off = r * 128 + ((c ^ (r & 7)) * 16);
        cp16(sb + off,         Qb + (size_t)(i0 + r) * H3 + c * 8);
        cp16(sb + 16384 + off, Kb + (size_t)r * H3 + c * 8);
        cp16(sb + 32768 + off, Vb + (size_t)r * H3 + c * 8);
    }
    cp_commit();
    #pragma unroll
    for (int t = 0; t < 4; t++) {
        int idx = tid + t * 256;
        int r = idx >> 3, c = idx & 7;
        uint32_t off = r * 128 + ((c ^ (r & 7)) * 16);
        cp16(sb + 49152 + off, Kb + (size_t)(128 + r) * H3 + c * 8);
        cp16(sb + 65536 + off, Vb + (size_t)(128 + r) * H3 + c * 8);
    }
    cp_commit();

    cp_wait1();
    __syncthreads();

    uint32_t aq[4][4];
    #pragma unroll
    for (int k16 = 0; k16 < 4; k16++) {
        int r = wm + (lane & 15);
        int ch = k16 * 2 + (lane >> 4);
        ldsm_x4(aq[k16][0], aq[k16][1], aq[k16][2], aq[k16][3],
                sb + r * 128 + ((ch ^ (r & 7)) * 16));
    }

    float m0 = -1e30f, m1 = -1e30f, l0 = 0.0f, l1 = 0.0f;
    float acc_o[8][4];
    #pragma unroll
    for (int i = 0; i < 8; i++)
        #pragma unroll
        for (int j = 0; j < 4; j++) acc_o[i][j] = 0.0f;

    for (int jt = 0; jt < 8; jt++) {
        if (jt < 7) cp_wait1(); else cp_wait0();
        __syncthreads();
        uint32_t ksb = sb + 16384 + (jt & 1) * 32768;
        uint32_t vsb = sb + 32768 + (jt & 1) * 32768;

        float s[16][4];
        #pragma unroll
        for (int n = 0; n < 16; n++)
            #pragma unroll
            for (int j = 0; j < 4; j++) s[n][j] = 0.0f;
        #pragma unroll
        for (int k16 = 0; k16 < 4; k16++) {
            #pragma unroll
            for (int nh = 0; nh < 8; nh++) {
                int r = nh * 16 + (lane & 15);
                int ch = k16 * 2 + (lane >> 4);
                uint32_t t0, t1, t2, t3;
                ldsm_x4(t0, t1, t2, t3, ksb + r * 128 + ((ch ^ (r & 7)) * 16));
                uint32_t b0[2] = {t0, t2}, b1[2] = {t1, t3};
                mma_bf16(s[nh * 2], aq[k16], b0);
                mma_bf16(s[nh * 2 + 1], aq[k16], b1);
            }
        }

        float mx0 = -1e30f, mx1 = -1e30f;
        #pragma unroll
        for (int n = 0; n < 16; n++) {
            s[n][0] *= 0.125f; s[n][1] *= 0.125f; s[n][2] *= 0.125f; s[n][3] *= 0.125f;
            mx0 = fmaxf(mx0, fmaxf(s[n][0], s[n][1]));
            mx1 = fmaxf(mx1, fmaxf(s[n][2], s[n][3]));
        }
        mx0 = fmaxf(mx0, __shfl_xor_sync(0xffffffffu, mx0, 1));
        mx0 = fmaxf(mx0, __shfl_xor_sync(0xffffffffu, mx0, 2));
        mx1 = fmaxf(mx1, __shfl_xor_sync(0xffffffffu, mx1, 1));
        mx1 = fmaxf(mx1, __shfl_xor_sync(0xffffffffu, mx1, 2));
        float mn0 = fmaxf(m0, mx0), mn1 = fmaxf(m1, mx1);
        float c0 = __expf(m0 - mn0), c1 = __expf(m1 - mn1);
        float sum0 = 0.0f, sum1 = 0.0f;
        #pragma unroll
        for (int n = 0; n < 16; n++) {
            s[n][0] = __expf(s[n][0] - mn0); s[n][1] = __expf(s[n][1] - mn0);
            s[n][2] = __expf(s[n][2] - mn1); s[n][3] = __expf(s[n][3] - mn1);
            sum0 += s[n][0] + s[n][1];
            sum1 += s[n][2] + s[n][3];
        }
        sum0 += __shfl_xor_sync(0xffffffffu, sum0, 1);
        sum0 += __shfl_xor_sync(0xffffffffu, sum0, 2);
        sum1 += __shfl_xor_sync(0xffffffffu, sum1, 1);
        sum1 += __shfl_xor_sync(0xffffffffu, sum1, 2);
        l0 = l0 * c0 + sum0; l1 = l1 * c1 + sum1;
        m0 = mn0; m1 = mn1;
        #pragma unroll
        for (int i = 0; i < 8; i++) {
            acc_o[i][0] *= c0; acc_o[i][1] *= c0;
            acc_o[i][2] *= c1; acc_o[i][3] *= c1;
        }

        uint32_t pa[8][4];
        #pragma unroll
        for (int kc = 0; kc < 8; kc++) {
            pa[kc][0] = pkbf(s[2 * kc][0], s[2 * kc][1]);
            pa[kc][1] = pkbf(s[2 * kc][2], s[2 * kc][3]);
            pa[kc][2] = pkbf(s[2 * kc + 1][0], s[2 * kc + 1][1]);
            pa[kc][3] = pkbf(s[2 * kc + 1][2], s[2 * kc + 1][3]);
        }

        #pragma unroll
        for (int kc = 0; kc < 8; kc++) {
            #pragma unroll
            for (int vh = 0; vh < 4; vh++) {
                int r = kc * 16 + (lane & 15);
                int ch = vh * 2 + (lane >> 4);
                uint32_t t0, t1, t2, t3;
                ldsm_x4_t(t0, t1, t2, t3, vsb + r * 128 + ((ch ^ (r & 7)) * 16));
                uint32_t b0[2] = {t0, t1}, b1[2] = {t2, t3};
                mma_bf16(acc_o[vh * 2], pa[kc], b0);
                mma_bf16(acc_o[vh * 2 + 1], pa[kc], b1);
            }
        }

        __syncthreads();
        int nj = jt + 2;
        if (nj < 8) {
            uint32_t kdst = sb + 16384 + (nj & 1) * 32768;
            uint32_t vdst = kdst + 16384;
            #pragma unroll
            for (int t = 0; t < 4; t++) {
                int idx = tid + t * 256;
                int r = idx >> 3, c = idx & 7;
                uint32_t off = r * 128 + ((c ^ (r & 7)) * 16);
                cp16(kdst + off, Kb + (size_t)(nj * 128 + r) * H3 + c * 8);
                cp16(vdst + off, Vb + (size_t)(nj * 128 + r) * H3 + c * 8);
            }
            cp_commit();
        }
    }

    float inv0 = 1.0f / l0, inv1 = 1.0f / l1;
    int r0 = i0 + wm + (lane >> 2);
    size_t base0 = ((size_t)b * SEQ + r0) * CDIM + h * HD;
    size_t base1 = base0 + 8 * CDIM;
    #pragma unroll
    for (int nt = 0; nt < 8; nt++) {
        int col = nt * 8 + (lane & 3) * 2;
        *(__nv_bfloat162*)(attn_out + base0 + col) =
            __float22bfloat162_rn(make_float2(acc_o[nt][0] * inv0, acc_o[nt][1] * inv0));
        *(__nv_bfloat162*)(attn_out + base1 + col) =
            __float22bfloat162_rn(make_float2(acc_o[nt][2] * inv1, acc_o[nt][3] * inv1));
    }
}

// ---------------- launch ----------------
extern "C" void kernel_launch(void* const* d_in, const int* in_sizes, int n_in,
                              void* d_out, int out_size) {
    const float* x      = (const float*)d_in[0];
    const float* ln1_g  = (const float*)d_in[1];
    const float* ln1_b  = (const float*)d_in[2];
    const float* w_qkv  = (const float*)d_in[3];
    const float* b_qkv  = (const float*)d_in[4];
    const float* w_proj = (const float*)d_in[5];
    const float* b_proj = (const float*)d_in[6];
    const float* gamma1 = (const float*)d_in[7];
    const float* ln2_g  = (const float*)d_in[8];
    const float* ln2_b  = (const float*)d_in[9];
    const float* w_fc1  = (const float*)d_in[10];
    const float* b_fc1  = (const float*)d_in[11];
    const float* w_fc2  = (const float*)d_in[12];
    const float* b_fc2  = (const float*)d_in[13];
    const float* gamma2 = (const float*)d_in[14];
    float* out = (float*)d_out;

    __nv_bfloat16 *ln, *qkv, *attn, *h, *wqkv, *wproj, *wfc1, *wfc2;
    float *x1;
    cudaGetSymbolAddress((void**)&ln,    g_ln_bf);
    cudaGetSymbolAddress((void**)&qkv,   g_qkv_bf);
    cudaGetSymbolAddress((void**)&attn,  g_attn_bf);
    cudaGetSymbolAddress((void**)&x1,    g_x1);
    cudaGetSymbolAddress((void**)&h,     g_h_bf);
    cudaGetSymbolAddress((void**)&wqkv,  g_wqkv_bf);
    cudaGetSymbolAddress((void**)&wproj, g_wproj_bf);
    cudaGetSymbolAddress((void**)&wfc1,  g_wfc1_bf);
    cudaGetSymbolAddress((void**)&wfc2,  g_wfc2_bf);

    cudaFuncSetAttribute(flash_attn_kernel, cudaFuncAttributeMaxDynamicSharedMemorySize, FA_SMEM);
    cudaFuncSetAttribute(gemm_bf16<0>, cudaFuncAttributeMaxDynamicSharedMemorySize, GSMEM);
    cudaFuncSetAttribute(gemm_bf16<1>, cudaFuncAttributeMaxDynamicSharedMemorySize, GSMEM);
    cudaFuncSetAttribute(gemm_bf16<2>, cudaFuncAttributeMaxDynamicSharedMemorySize, GSMEM);

    // merged weight conversion
    f2bf4_kernel<<<(N0 + N1 + N2 + N3) / 4 / 256, 256>>>(w_qkv, w_proj, w_fc1, w_fc2,
                                                         wqkv, wproj, wfc1, wfc2);

    // 1) ln1
    ln_kernel<<<MROWS, 256>>>(x, ln1_g, ln1_b, ln);
    // 2) qkv = ln @ w_qkv + b_qkv  (bf16 out)
    gemm_bf16<0><<<dim3(H3 / 128, MROWS / 128), 128, GSMEM>>>(ln, wqkv, b_qkv, nullptr, nullptr, qkv, MROWS, H3, CDIM);
    // 3) fused attention -> attn (bf16)
    flash_attn_kernel<<<dim3(8, BHEAD), 256, FA_SMEM>>>(qkv, attn);
    // 4) x1 = x + gamma1 * (attn @ w_proj + b_proj)  (fp32 out)
    gemm_bf16<1><<<dim3(CDIM / 128, MROWS / 128), 128, GSMEM>>>(attn, wproj, b_proj, x, gamma1, x1, MROWS, CDIM, CDIM);
    // 5) ln2
    ln_kernel<<<MROWS, 256>>>(x1, ln2_g, ln2_b, ln);
    // 6) h = gelu(ln @ w_fc1 + b_fc1)  (bf16 out)
    gemm_bf16<2><<<dim3(HID / 128, MROWS / 128), 128, GSMEM>>>(ln, wfc1, b_fc1, nullptr, nullptr, h, MROWS, HID, CDIM);
    // 7) out = x1 + gamma2 * (h @ w_fc2 + b_fc2)  (fp32 out)
    gemm_bf16<1><<<dim3(CDIM / 128, MROWS / 128), 128, GSMEM>>>(h, wfc2, b_fc2, x1, gamma2, out, MROWS, CDIM, HID);
}

// round 6
// speedup vs baseline: 8.8464x; 1.0246x over previous
#include <cuda_runtime.h>
#include <cuda_bf16.h>
#include <math.h>
#include <stdint.h>

// Problem constants
#define BATCH 8
#define SEQ   1024
#define CDIM  768
#define HEADS 12
#define HD    64
#define H3    2304
#define HID   3072
#define MROWS (BATCH*SEQ)        // 8192
#define BHEAD (BATCH*HEADS)      // 96
#define LN_EPS 1e-3f

// ---------------- static scratch ----------------
__device__ __nv_bfloat16 g_ln_bf[MROWS * CDIM];
__device__ __nv_bfloat16 g_qkv_bf[MROWS * H3];
__device__ __nv_bfloat16 g_attn_bf[MROWS * CDIM];
__device__ float         g_x1[MROWS * CDIM];
__device__ __nv_bfloat16 g_h_bf[MROWS * HID];
__device__ __nv_bfloat16 g_wqkv_bf[CDIM * H3];
__device__ __nv_bfloat16 g_wproj_bf[CDIM * CDIM];
__device__ __nv_bfloat16 g_wfc1_bf[CDIM * HID];
__device__ __nv_bfloat16 g_wfc2_bf[HID * CDIM];

// ---------------- PTX helpers ----------------
__device__ __forceinline__ uint32_t cvta_smem(const void* p) {
    return (uint32_t)__cvta_generic_to_shared(p);
}
__device__ __forceinline__ void ldsm_x4(uint32_t& r0, uint32_t& r1, uint32_t& r2, uint32_t& r3, uint32_t a) {
    asm volatile("ldmatrix.sync.aligned.m8n8.x4.shared.b16 {%0,%1,%2,%3},[%4];"
                 : "=r"(r0), "=r"(r1), "=r"(r2), "=r"(r3) : "r"(a));
}
__device__ __forceinline__ void ldsm_x4_t(uint32_t& r0, uint32_t& r1, uint32_t& r2, uint32_t& r3, uint32_t a) {
    asm volatile("ldmatrix.sync.aligned.m8n8.x4.trans.shared.b16 {%0,%1,%2,%3},[%4];"
                 : "=r"(r0), "=r"(r1), "=r"(r2), "=r"(r3) : "r"(a));
}
__device__ __forceinline__ void mma_bf16(float* c, const uint32_t* a, const uint32_t* b) {
    asm volatile("mma.sync.aligned.m16n8k16.row.col.f32.bf16.bf16.f32 "
                 "{%0,%1,%2,%3},{%4,%5,%6,%7},{%8,%9},{%0,%1,%2,%3};"
                 : "+f"(c[0]), "+f"(c[1]), "+f"(c[2]), "+f"(c[3])
                 : "r"(a[0]), "r"(a[1]), "r"(a[2]), "r"(a[3]), "r"(b[0]), "r"(b[1]));
}
__device__ __forceinline__ void cp16(uint32_t saddr, const void* g) {
    asm volatile("cp.async.cg.shared.global [%0],[%1],16;" :: "r"(saddr), "l"(g));
}
__device__ __forceinline__ void cp_commit() { asm volatile("cp.async.commit_group;"); }
__device__ __forceinline__ void cp_wait0()  { asm volatile("cp.async.wait_group 0;"); }
__device__ __forceinline__ void cp_wait1()  { asm volatile("cp.async.wait_group 1;"); }
__device__ __forceinline__ uint32_t pkbf(float x, float y) {
    __nv_bfloat162 t = __float22bfloat162_rn(make_float2(x, y));
    return *(uint32_t*)&t;
}

// ---------------- merged fp32 -> bf16 weight convert ----------------
#define N0 (CDIM*H3)
#define N1 (CDIM*CDIM)
#define N2 (CDIM*HID)
#define N3 (HID*CDIM)
__global__ void f2bf4_kernel(const float* __restrict__ w0, const float* __restrict__ w1,
                             const float* __restrict__ w2, const float* __restrict__ w3,
                             __nv_bfloat16* __restrict__ o0, __nv_bfloat16* __restrict__ o1,
                             __nv_bfloat16* __restrict__ o2, __nv_bfloat16* __restrict__ o3) {
    int i = (blockIdx.x * blockDim.x + threadIdx.x) * 4;
    const float* src; __nv_bfloat16* dst; int off;
    if (i < N0)                { src = w0; dst = o0; off = i; }
    else if (i < N0+N1)        { src = w1; dst = o1; off = i - N0; }
    else if (i < N0+N1+N2)     { src = w2; dst = o2; off = i - N0 - N1; }
    else                       { src = w3; dst = o3; off = i - N0 - N1 - N2; }
    float4 v = *(const float4*)(src + off);
    __nv_bfloat162* o = (__nv_bfloat162*)(dst + off);
    o[0] = __float22bfloat162_rn(make_float2(v.x, v.y));
    o[1] = __float22bfloat162_rn(make_float2(v.z, v.w));
}

// ---------------- reductions ----------------
__device__ __forceinline__ float block_reduce_sum(float v, float* sh) {
    __syncthreads();
    #pragma unroll
    for (int o = 16; o > 0; o >>= 1) v += __shfl_xor_sync(0xffffffffu, v, o);
    int warp = threadIdx.x >> 5, lane = threadIdx.x & 31;
    if (lane == 0) sh[warp] = v;
    __syncthreads();
    if (warp == 0) {
        v = (lane < (blockDim.x >> 5)) ? sh[lane] : 0.0f;
        #pragma unroll
        for (int o = 4; o > 0; o >>= 1) v += __shfl_xor_sync(0xffffffffu, v, o);
        if (lane == 0) sh[0] = v;
    }
    __syncthreads();
    return sh[0];
}

// ---------------- LayerNorm (fp32 in -> bf16 out) ----------------
__global__ void ln_kernel(const float* __restrict__ x, const float* __restrict__ g,
                          const float* __restrict__ b, __nv_bfloat16* __restrict__ out) {
    __shared__ float sh[32];
    int row = blockIdx.x;
    int t = threadIdx.x;
    const float* xr = x + (size_t)row * CDIM;
    float v0 = xr[t], v1 = xr[t + 256], v2 = xr[t + 512];
    float s = block_reduce_sum(v0 + v1 + v2, sh);
    float mu = s * (1.0f / CDIM);
    float d0 = v0 - mu, d1 = v1 - mu, d2 = v2 - mu;
    float s2 = block_reduce_sum(d0 * d0 + d1 * d1 + d2 * d2, sh);
    float rstd = rsqrtf(s2 * (1.0f / CDIM) + LN_EPS);
    __nv_bfloat16* outr = out + (size_t)row * CDIM;
    outr[t]       = __float2bfloat16(d0 * rstd * g[t]       + b[t]);
    outr[t + 256] = __float2bfloat16(d1 * rstd * g[t + 256] + b[t + 256]);
    outr[t + 512] = __float2bfloat16(d2 * rstd * g[t + 512] + b[t + 512]);
}

// ---------------- bf16 GEMM: 128x128 CTA, 4 warps (2x2) of 64x64, K-block 64, 3-stage ----------------
#define GSTAGE 32768
#define GSMEM  (3 * GSTAGE)

template<int MODE>
__global__ __launch_bounds__(128, 2) void gemm_bf16(
    const __nv_bfloat16* __restrict__ A, const __nv_bfloat16* __restrict__ B,
    const float* __restrict__ bias, const float* __restrict__ res,
    const float* __restrict__ gamma, void* __restrict__ Cout,
    int M, int N, int K)
{
    extern __shared__ char gsm[];
    uint32_t sb = cvta_smem(gsm);

    int tid = threadIdx.x, lane = tid & 31, warp = tid >> 5;
    int wm = (warp >> 1) * 64, wn = (warp & 1) * 64;
    int bx = blockIdx.x, by = blockIdx.y;

    int ar = tid >> 3, ac = tid & 7;
    int br = tid >> 4, bc = tid & 15;
    const __nv_bfloat16* Ag = A + (size_t)(by * 128 + ar) * K + ac * 8;
    const __nv_bfloat16* Bg = B + (size_t)br * N + bx * 128 + bc * 8;
    uint32_t a_soff = ar * 128 + ((ac ^ (ar & 7)) * 16);
    uint32_t b_soff = 16384 + br * 256 + ((bc ^ (br & 7)) * 16);

    float acc[4][8][4];
    #pragma unroll
    for (int i = 0; i < 4; i++)
        #pragma unroll
        for (int j = 0; j < 8; j++)
            #pragma unroll
            for (int k = 0; k < 4; k++) acc[i][j][k] = 0.0f;

    int KB = K >> 6;

    #pragma unroll
    for (int pb = 0; pb < 2; pb++) {
        uint32_t st = sb + pb * GSTAGE;
        const __nv_bfloat16* Ak = Ag + pb * 64;
        const __nv_bfloat16* Bk = Bg + (size_t)pb * 64 * N;
        #pragma unroll
        for (int t = 0; t < 8; t++) cp16(st + a_soff + t * 2048, Ak + (size_t)t * 16 * K);
        #pragma unroll
        for (int t = 0; t < 8; t++) cp16(st + b_soff + t * 2048, Bk + (size_t)t * 8 * N);
        cp_commit();
    }

    int stage = 0;
    for (int kb = 0; kb < KB; kb++) {
        if (kb + 1 < KB) cp_wait1(); else cp_wait0();
        __syncthreads();
        uint32_t st = sb + stage * GSTAGE;

        #pragma unroll
        for (int k16 = 0; k16 < 4; k16++) {
            uint32_t af[4][4];
            #pragma unroll
            for (int mi = 0; mi < 4; mi++) {
                int r = wm + mi * 16 + (lane & 15);
                int ch = k16 * 2 + (lane >> 4);
                ldsm_x4(af[mi][0], af[mi][1], af[mi][2], af[mi][3],
                        st + r * 128 + ((ch ^ (r & 7)) * 16));
            }
            uint32_t bf[8][2];
            #pragma unroll
            for (int nh = 0; nh < 4; nh++) {
                int r = k16 * 16 + (lane & 15);
                int ch = (wn >> 3) + nh * 2 + (lane >> 4);
                uint32_t t0, t1, t2, t3;
                ldsm_x4_t(t0, t1, t2, t3, st + 16384 + r * 256 + ((ch ^ (r & 7)) * 16));
                bf[nh * 2][0] = t0; bf[nh * 2][1] = t1;
                bf[nh * 2 + 1][0] = t2; bf[nh * 2 + 1][1] = t3;
            }
            #pragma unroll
            for (int mi = 0; mi < 4; mi++)
                #pragma unroll
                for (int ni = 0; ni < 8; ni++)
                    mma_bf16(acc[mi][ni], af[mi], bf[ni]);
        }

        int nb = kb + 2;
        if (nb < KB) {
            uint32_t ld = sb + ((stage + 2) % 3) * GSTAGE;
            const __nv_bfloat16* Ak = Ag + nb * 64;
            const __nv_bfloat16* Bk = Bg + (size_t)nb * 64 * N;
            #pragma unroll
            for (int t = 0; t < 8; t++) cp16(ld + a_soff + t * 2048, Ak + (size_t)t * 16 * K);
            #pragma unroll
            for (int t = 0; t < 8; t++) cp16(ld + b_soff + t * 2048, Bk + (size_t)t * 8 * N);
            cp_commit();
        }
        stage = (stage + 1) % 3;
    }

    #pragma unroll
    for (int mi = 0; mi < 4; mi++) {
        #pragma unroll
        for (int ni = 0; ni < 8; ni++) {
            #pragma unroll
            for (int hh = 0; hh < 2; hh++) {
                int row = by * 128 + wm + mi * 16 + (lane >> 2) + hh * 8;
                int col = bx * 128 + wn + ni * 8 + (lane & 3) * 2;
                float vx = acc[mi][ni][hh * 2]     + bias[col];
                float vy = acc[mi][ni][hh * 2 + 1] + bias[col + 1];
                size_t off = (size_t)row * N + col;
                if (MODE == 1) {
                    float* C = (float*)Cout;
                    float2 r = *(const float2*)(res + off);
                    float2 o;
                    o.x = r.x + gamma[col]     * vx;
                    o.y = r.y + gamma[col + 1] * vy;
                    *(float2*)(C + off) = o;
                } else {
                    if (MODE == 2) {
                        vx = 0.5f * vx * (1.0f + erff(vx * 0.70710678118654752f));
                        vy = 0.5f * vy * (1.0f + erff(vy * 0.70710678118654752f));
                    }
                    __nv_bfloat16* C = (__nv_bfloat16*)Cout;
                    *(__nv_bfloat162*)(C + off) = __float22bfloat162_rn(make_float2(vx, vy));
                }
            }
        }
    }
}

// ---------------- fused flash attention (64-row KV chunks, 2 CTAs/SM) ----------------
// grid (8 itiles, 96 bh), 256 threads (8 warps). Warp w owns q-rows wm = w*16.
// smem: Q[128x64] @0 (16KB); 2 KV buffers of [K 64x64 (8KB) + V 64x64 (8KB)] -> 48KB total.
#define FA_SMEM (16384 + 2 * 16384)
#define LOG2E_SCALE 0.18033688011112042f   // log2(e) * 0.125

__global__ __launch_bounds__(256, 2) void flash_attn_kernel(const __nv_bfloat16* __restrict__ qkv,
                                                            __nv_bfloat16* __restrict__ attn_out) {
    extern __shared__ char fsm[];
    uint32_t sb = cvta_smem(fsm);
    int bh = blockIdx.y;
    int b = bh / HEADS, h = bh % HEADS;
    int i0 = blockIdx.x * 128;
    int tid = threadIdx.x, lane = tid & 31, w = tid >> 5;
    int wm = w * 16;

    const __nv_bfloat16* Qb = qkv + (size_t)b * SEQ * H3 + h * HD;
    const __nv_bfloat16* Kb = Qb + CDIM;
    const __nv_bfloat16* Vb = Qb + 2 * CDIM;

    // chunk 0 loads: Q (4/thread) + K0,V0 (2+2/thread)
    #pragma unroll
    for (int t = 0; t < 4; t++) {
        int idx = tid + t * 256;
        int r = idx >> 3, c = idx & 7;
        cp16(sb + r * 128 + ((c ^ (r & 7)) * 16), Qb + (size_t)(i0 + r) * H3 + c * 8);
    }
    #pragma unroll
    for (int t = 0; t < 2; t++) {
        int idx = tid + t * 256;
        int r = idx >> 3, c = idx & 7;
        uint32_t off = r * 128 + ((c ^ (r & 7)) * 16);
        cp16(sb + 16384 + off,        Kb + (size_t)r * H3 + c * 8);
        cp16(sb + 16384 + 8192 + off, Vb + (size_t)r * H3 + c * 8);
    }
    cp_commit();
    // chunk 1
    #pragma unroll
    for (int t = 0; t < 2; t++) {
        int idx = tid + t * 256;
        int r = idx >> 3, c = idx & 7;
        uint32_t off = r * 128 + ((c ^ (r & 7)) * 16);
        cp16(sb + 32768 + off,        Kb + (size_t)(64 + r) * H3 + c * 8);
        cp16(sb + 32768 + 8192 + off, Vb + (size_t)(64 + r) * H3 + c * 8);
    }
    cp_commit();

    cp_wait1();
    __syncthreads();

    // Q fragments, register-resident
    uint32_t aq[4][4];
    #pragma unroll
    for (int k16 = 0; k16 < 4; k16++) {
        int r = wm + (lane & 15);
        int ch = k16 * 2 + (lane >> 4);
        ldsm_x4(aq[k16][0], aq[k16][1], aq[k16][2], aq[k16][3],
                sb + r * 128 + ((ch ^ (r & 7)) * 16));
    }

    float m0 = -1e30f, m1 = -1e30f, l0 = 0.0f, l1 = 0.0f;
    float acc_o[8][4];
    #pragma unroll
    for (int i = 0; i < 8; i++)
        #pragma unroll
        for (int j = 0; j < 4; j++) acc_o[i][j] = 0.0f;

    for (int jt = 0; jt < 16; jt++) {
        if (jt < 15) cp_wait1(); else cp_wait0();
        __syncthreads();
        uint32_t ksb = sb + 16384 + (jt & 1) * 16384;
        uint32_t vsb = ksb + 8192;

        // S = Q @ K^T (16 q-rows x 64 j-cols per warp)
        float s[8][4];
        #pragma unroll
        for (int n = 0; n < 8; n++)
            #pragma unroll
            for (int j = 0; j < 4; j++) s[n][j] = 0.0f;
        #pragma unroll
        for (int k16 = 0; k16 < 4; k16++) {
            #pragma unroll
            for (int nh = 0; nh < 4; nh++) {
                int r = nh * 16 + (lane & 15);
                int ch = k16 * 2 + (lane >> 4);
                uint32_t t0, t1, t2, t3;
                ldsm_x4(t0, t1, t2, t3, ksb + r * 128 + ((ch ^ (r & 7)) * 16));
                uint32_t b0[2] = {t0, t2}, b1[2] = {t1, t3};
                mma_bf16(s[nh * 2], aq[k16], b0);
                mma_bf16(s[nh * 2 + 1], aq[k16], b1);
            }
        }

        // log2-domain online softmax (scale folded into LOG2E_SCALE)
        float mx0 = -1e30f, mx1 = -1e30f;
        #pragma unroll
        for (int n = 0; n < 8; n++) {
            s[n][0] *= LOG2E_SCALE; s[n][1] *= LOG2E_SCALE;
            s[n][2] *= LOG2E_SCALE; s[n][3] *= LOG2E_SCALE;
            mx0 = fmaxf(mx0, fmaxf(s[n][0], s[n][1]));
            mx1 = fmaxf(mx1, fmaxf(s[n][2], s[n][3]));
        }
        mx0 = fmaxf(mx0, __shfl_xor_sync(0xffffffffu, mx0, 1));
        mx0 = fmaxf(mx0, __shfl_xor_sync(0xffffffffu, mx0, 2));
        mx1 = fmaxf(mx1, __shfl_xor_sync(0xffffffffu, mx1, 1));
        mx1 = fmaxf(mx1, __shfl_xor_sync(0xffffffffu, mx1, 2));
        float mn0 = fmaxf(m0, mx0), mn1 = fmaxf(m1, mx1);
        float c0 = exp2f(m0 - mn0), c1 = exp2f(m1 - mn1);
        float sum0 = 0.0f, sum1 = 0.0f;
        #pragma unroll
        for (int n = 0; n < 8; n++) {
            s[n][0] = exp2f(s[n][0] - mn0); s[n][1] = exp2f(s[n][1] - mn0);
            s[n][2] = exp2f(s[n][2] - mn1); s[n][3] = exp2f(s[n][3] - mn1);
            sum0 += s[n][0] + s[n][1];
            sum1 += s[n][2] + s[n][3];
        }
        sum0 += __shfl_xor_sync(0xffffffffu, sum0, 1);
        sum0 += __shfl_xor_sync(0xffffffffu, sum0, 2);
        sum1 += __shfl_xor_sync(0xffffffffu, sum1, 1);
        sum1 += __shfl_xor_sync(0xffffffffu, sum1, 2);
        l0 = l0 * c0 + sum0; l1 = l1 * c1 + sum1;
        m0 = mn0; m1 = mn1;
        #pragma unroll
        for (int i = 0; i < 8; i++) {
            acc_o[i][0] *= c0; acc_o[i][1] *= c0;
            acc_o[i][2] *= c1; acc_o[i][3] *= c1;
        }

        // pack P (16 x 64) -> 4 k16 A-fragments
        uint32_t pa[4][4];
        #pragma unroll
        for (int kc = 0; kc < 4; kc++) {
            pa[kc][0] = pkbf(s[2 * kc][0], s[2 * kc][1]);
            pa[kc][1] = pkbf(s[2 * kc][2], s[2 * kc][3]);
            pa[kc][2] = pkbf(s[2 * kc + 1][0], s[2 * kc + 1][1]);
            pa[kc][3] = pkbf(s[2 * kc + 1][2], s[2 * kc + 1][3]);
        }

        // O += P @ V  (k = 64 over this chunk)
        #pragma unroll
        for (int kc = 0; kc < 4; kc++) {
            #pragma unroll
            for (int vh = 0; vh < 4; vh++) {
                int r = kc * 16 + (lane & 15);
                int ch = vh * 2 + (lane >> 4);
                uint32_t t0, t1, t2, t3;
                ldsm_x4_t(t0, t1, t2, t3, vsb + r * 128 + ((ch ^ (r & 7)) * 16));
                uint32_t b0[2] = {t0, t1}, b1[2] = {t2, t3};
                mma_bf16(acc_o[vh * 2], pa[kc], b0);
                mma_bf16(acc_o[vh * 2 + 1], pa[kc], b1);
            }
        }

        __syncthreads();
        int nj = jt + 2;
        if (nj < 16) {
            uint32_t kdst = sb + 16384 + (nj & 1) * 16384;
            uint32_t vdst = kdst + 8192;
            #pragma unroll
            for (int t = 0; t < 2; t++) {
                int idx = tid + t * 256;
                int r = idx >> 3, c = idx & 7;
                uint32_t off = r * 128 + ((c ^ (r & 7)) * 16);
                cp16(kdst + off, Kb + (size_t)(nj * 64 + r) * H3 + c * 8);
                cp16(vdst + off, Vb + (size_t)(nj * 64 + r) * H3 + c * 8);
            }
            cp_commit();
        }
    }

    float inv0 = 1.0f / l0, inv1 = 1.0f / l1;
    int r0 = i0 + wm + (lane >> 2);
    size_t base0 = ((size_t)b * SEQ + r0) * CDIM + h * HD;
    size_t base1 = base0 + 8 * CDIM;
    #pragma unroll
    for (int nt = 0; nt < 8; nt++) {
        int col = nt * 8 + (lane & 3) * 2;
        *(__nv_bfloat162*)(attn_out + base0 + col) =
            __float22bfloat162_rn(make_float2(acc_o[nt][0] * inv0, acc_o[nt][1] * inv0));
        *(__nv_bfloat162*)(attn_out + base1 + col) =
            __float22bfloat162_rn(make_float2(acc_o[nt][2] * inv1, acc_o[nt][3] * inv1));
    }
}

// ---------------- launch ----------------
extern "C" void kernel_launch(void* const* d_in, const int* in_sizes, int n_in,
                              void* d_out, int out_size) {
    const float* x      = (const float*)d_in[0];
    const float* ln1_g  = (const float*)d_in[1];
    const float* ln1_b  = (const float*)d_in[2];
    const float* w_qkv  = (const float*)d_in[3];
    const float* b_qkv  = (const float*)d_in[4];
    const float* w_proj = (const float*)d_in[5];
    const float* b_proj = (const float*)d_in[6];
    const float* gamma1 = (const float*)d_in[7];
    const float* ln2_g  = (const float*)d_in[8];
    const float* ln2_b  = (const float*)d_in[9];
    const float* w_fc1  = (const float*)d_in[10];
    const float* b_fc1  = (const float*)d_in[11];
    const float* w_fc2  = (const float*)d_in[12];
    const float* b_fc2  = (const float*)d_in[13];
    const float* gamma2 = (const float*)d_in[14];
    float* out = (float*)d_out;

    __nv_bfloat16 *ln, *qkv, *attn, *h, *wqkv, *wproj, *wfc1, *wfc2;
    float *x1;
    cudaGetSymbolAddress((void**)&ln,    g_ln_bf);
    cudaGetSymbolAddress((void**)&qkv,   g_qkv_bf);
    cudaGetSymbolAddress((void**)&attn,  g_attn_bf);
    cudaGetSymbolAddress((void**)&x1,    g_x1);
    cudaGetSymbolAddress((void**)&h,     g_h_bf);
    cudaGetSymbolAddress((void**)&wqkv,  g_wqkv_bf);
    cudaGetSymbolAddress((void**)&wproj, g_wproj_bf);
    cudaGetSymbolAddress((void**)&wfc1,  g_wfc1_bf);
    cudaGetSymbolAddress((void**)&wfc2,  g_wfc2_bf);

    cudaFuncSetAttribute(flash_attn_kernel, cudaFuncAttributeMaxDynamicSharedMemorySize, FA_SMEM);
    cudaFuncSetAttribute(gemm_bf16<0>, cudaFuncAttributeMaxDynamicSharedMemorySize, GSMEM);
    cudaFuncSetAttribute(gemm_bf16<1>, cudaFuncAttributeMaxDynamicSharedMemorySize, GSMEM);
    cudaFuncSetAttribute(gemm_bf16<2>, cudaFuncAttributeMaxDynamicSharedMemorySize, GSMEM);

    // merged weight conversion
    f2bf4_kernel<<<(N0 + N1 + N2 + N3) / 4 / 256, 256>>>(w_qkv, w_proj, w_fc1, w_fc2,
                                                         wqkv, wproj, wfc1, wfc2);

    // 1) ln1
    ln_kernel<<<MROWS, 256>>>(x, ln1_g, ln1_b, ln);
    // 2) qkv = ln @ w_qkv + b_qkv  (bf16 out)
    gemm_bf16<0><<<dim3(H3 / 128, MROWS / 128), 128, GSMEM>>>(ln, wqkv, b_qkv, nullptr, nullptr, qkv, MROWS, H3, CDIM);
    // 3) fused attention -> attn (bf16)
    flash_attn_kernel<<<dim3(8, BHEAD), 256, FA_SMEM>>>(qkv, attn);
    // 4) x1 = x + gamma1 * (attn @ w_proj + b_proj)  (fp32 out)
    gemm_bf16<1><<<dim3(CDIM / 128, MROWS / 128), 128, GSMEM>>>(attn, wproj, b_proj, x, gamma1, x1, MROWS, CDIM, CDIM);
    // 5) ln2
    ln_kernel<<<MROWS, 256>>>(x1, ln2_g, ln2_b, ln);
    // 6) h = gelu(ln @ w_fc1 + b_fc1)  (bf16 out)
    gemm_bf16<2><<<dim3(HID / 128, MROWS / 128), 128, GSMEM>>>(ln, wfc1, b_fc1, nullptr, nullptr, h, MROWS, HID, CDIM);
    // 7) out = x1 + gamma2 * (h @ w_fc2 + b_fc2)  (fp32 out)
    gemm_bf16<1><<<dim3(CDIM / 128, MROWS / 128), 128, GSMEM>>>(h, wfc2, b_fc2, x1, gamma2, out, MROWS, CDIM, HID);
}